// round 14
// baseline (speedup 1.0000x reference)
#include <cuda_runtime.h>
#include <cuda_bf16.h>
#include <math.h>
#include <stdint.h>

// Problem constants
#define D   512
#define QN  16
#define NT  4096   // B*L tokens
#define NG  512    // N gathered groups
#define PP  64     // group size P

#define SCALE 0.04419417382415922f  // 1/sqrt(512)

// Scratch (allocation-free: __device__ globals)
__device__ float g_Vp[NT * D];            // patch @ Wv + bv      [4096,512]
__device__ __nv_bfloat16 g_Ahi[NT * D];   // bf16 hi split of patch
__device__ __nv_bfloat16 g_Alo[NT * D];   // bf16 lo split of patch
__device__ __nv_bfloat16 g_Bhi[D * D];    // bf16 hi split of Wv^T ([n][k])
__device__ __nv_bfloat16 g_Blo[D * D];    // bf16 lo split of Wv^T
__device__ float g_sp[NT * QN];           // scaled patch scores  [4096,16]
__device__ float g_VQ[QN * D];            // Q0 @ Wv + bv         [16,512]
__device__ float g_Ak[QN * D];            // (Wk @ Q0^T)^T        [16,512]
__device__ float g_pf[NT];                // pf[t] = patch[t].u + cw (== Vp.Wf)
__device__ float g_u[D];                  // Wv @ Wf              [512]
__device__ float g_cw;                    // bv . Wf
__device__ float g_tq[QN];                // VQ @ Wf              [16]
__device__ float g_sself[QN];             // self-token scores    [16]
__device__ float g_qbk[QN];               // Q0[q] . bk           [16]
__device__ float g_es[NG][PP];            // effective gather weights
__device__ float g_c0[NG][QN];            // VQ-term coefficients
__device__ int   g_sidx[NG][PP];          // cached indices

// ---- PTX helpers (all sm_80-level, valid for compute_103 target) -----------
__device__ __forceinline__ uint32_t smem_u32(const void* p) {
    uint32_t a;
    asm("{ .reg .u64 tmp; cvta.to.shared.u64 tmp, %1; cvt.u32.u64 %0, tmp; }"
        : "=r"(a) : "l"(p));
    return a;
}
__device__ __forceinline__ void cp16(uint32_t sdst, const void* gsrc) {
    asm volatile("cp.async.cg.shared.global [%0], [%1], 16;"
                 :: "r"(sdst), "l"(gsrc) : "memory");
}
#define CP_COMMIT() asm volatile("cp.async.commit_group;" ::: "memory")
#define CP_WAIT(n)  asm volatile("cp.async.wait_group %0;" :: "n"(n) : "memory")

__device__ __forceinline__ void ldm_x4(uint32_t* r, uint32_t addr) {
    asm volatile("ldmatrix.sync.aligned.m8n8.x4.shared.b16 {%0,%1,%2,%3}, [%4];"
                 : "=r"(r[0]), "=r"(r[1]), "=r"(r[2]), "=r"(r[3]) : "r"(addr));
}
__device__ __forceinline__ void mma16816(float* c, const uint32_t* a, const uint32_t* b) {
    asm volatile("mma.sync.aligned.m16n8k16.row.col.f32.bf16.bf16.f32 "
                 "{%0,%1,%2,%3}, {%4,%5,%6,%7}, {%8,%9}, {%0,%1,%2,%3};"
                 : "+f"(c[0]), "+f"(c[1]), "+f"(c[2]), "+f"(c[3])
                 : "r"(a[0]), "r"(a[1]), "r"(a[2]), "r"(a[3]), "r"(b[0]), "r"(b[1]));
}

// ---------------------------------------------------------------------------
// k_pre: grid (16, 3), block 512.
//  y==0: VQ[q] (float4 col-groups) + tq[q]
//  y==1: Ak[q][t] + qbk / sself reductions
//  y==2: u = Wv @ Wf (block x -> 32 rows) ; block x==0 also cw = bv.Wf
// ---------------------------------------------------------------------------
__global__ void k_pre(const float* __restrict__ query, const float* __restrict__ Wk,
                      const float* __restrict__ Wv, const float* __restrict__ bv,
                      const float* __restrict__ bk, const float* __restrict__ Wf) {
    __shared__ float q0[D];
    __shared__ float red[2][16];
    __shared__ __align__(16) float4 part4[4][128];
    int q = blockIdx.x, t = threadIdx.x;
    int w = t >> 5, lane = t & 31;

    if (blockIdx.y == 2) {
        q0[t] = Wf[t];
        __syncthreads();
#pragma unroll
        for (int hh = 0; hh < 2; hh++) {
            int r = blockIdx.x * 32 + hh * 16 + w;
            const float* row = Wv + (size_t)r * D;
            float s = 0.f;
#pragma unroll
            for (int i = 0; i < D / 32; i++) s += row[lane + i * 32] * q0[lane + i * 32];
#pragma unroll
            for (int o = 16; o; o >>= 1) s += __shfl_xor_sync(0xffffffffu, s, o);
            if (lane == 0) g_u[r] = s;
        }
        if (blockIdx.x == 0) {
            float r1 = bv[t] * q0[t];
#pragma unroll
            for (int o = 16; o; o >>= 1) r1 += __shfl_xor_sync(0xffffffffu, r1, o);
            if (lane == 0) red[0][w] = r1;
            __syncthreads();
            if (t == 0) {
                float s = 0.f;
#pragma unroll
                for (int i = 0; i < 16; i++) s += red[0][i];
                g_cw = s;
            }
        }
        return;
    }

    q0[t] = query[q * D + t];
    __syncthreads();

    if (blockIdx.y == 0) {
        int cg = t & 127, rc = t >> 7;
        const float4* Wv4 = reinterpret_cast<const float4*>(Wv);
        float4 a = make_float4(0.f, 0.f, 0.f, 0.f);
#pragma unroll 8
        for (int i = 0; i < 128; i++) {
            int d = rc * 128 + i;
            float qd = q0[d];
            float4 wv = Wv4[(size_t)d * 128 + cg];
            a.x += qd * wv.x; a.y += qd * wv.y;
            a.z += qd * wv.z; a.w += qd * wv.w;
        }
        part4[rc][cg] = a;
        __syncthreads();
        float tqv = 0.f;
        if (t < 128) {
            float4 r = part4[0][t], p1 = part4[1][t], p2 = part4[2][t], p3 = part4[3][t];
            float4 bv4 = reinterpret_cast<const float4*>(bv)[t];
            r.x += p1.x + p2.x + p3.x + bv4.x;
            r.y += p1.y + p2.y + p3.y + bv4.y;
            r.z += p1.z + p2.z + p3.z + bv4.z;
            r.w += p1.w + p2.w + p3.w + bv4.w;
            reinterpret_cast<float4*>(g_VQ)[q * 128 + t] = r;
            float4 wf = reinterpret_cast<const float4*>(Wf)[t];
            tqv = r.x * wf.x + r.y * wf.y + r.z * wf.z + r.w * wf.w;
        }
#pragma unroll
        for (int o = 16; o; o >>= 1) tqv += __shfl_xor_sync(0xffffffffu, tqv, o);
        if (lane == 0 && w < 4) red[0][w] = tqv;
        __syncthreads();
        if (t == 0) g_tq[q] = red[0][0] + red[0][1] + red[0][2] + red[0][3];
    } else {
        const float4* wr = reinterpret_cast<const float4*>(Wk + (size_t)t * D);
        float a0 = 0.f, a1 = 0.f;
#pragma unroll 8
        for (int i = 0; i < D / 8; i++) {
            float4 w0 = wr[2 * i], w1 = wr[2 * i + 1];
            a0 += w0.x * q0[8*i+0] + w0.y * q0[8*i+1] + w0.z * q0[8*i+2] + w0.w * q0[8*i+3];
            a1 += w1.x * q0[8*i+4] + w1.y * q0[8*i+5] + w1.z * q0[8*i+6] + w1.w * q0[8*i+7];
        }
        float r = a0 + a1;
        g_Ak[q * D + t] = r;
        float r0v = q0[t] * r;
        float r1v = q0[t] * bk[t];
#pragma unroll
        for (int o = 16; o; o >>= 1) {
            r0v += __shfl_xor_sync(0xffffffffu, r0v, o);
            r1v += __shfl_xor_sync(0xffffffffu, r1v, o);
        }
        if (lane == 0) { red[0][w] = r0v; red[1][w] = r1v; }
        __syncthreads();
        if (w == 0) {
            float x0 = (lane < 16) ? red[0][lane] : 0.f;
            float x1 = (lane < 16) ? red[1][lane] : 0.f;
#pragma unroll
            for (int o = 8; o; o >>= 1) {
                x0 += __shfl_xor_sync(0xffffffffu, x0, o);
                x1 += __shfl_xor_sync(0xffffffffu, x1, o);
            }
            if (lane == 0) {
                g_qbk[q] = x1;
                g_sself[q] = (x0 + x1) * SCALE;
            }
        }
    }
}

// ---------------------------------------------------------------------------
// k_sp: fused. Blocks 0..255: sp scores + pf (17th accumulator) + bf16 splits
// for 16 token rows. Blocks 256..319: Wv transpose/split.
// ---------------------------------------------------------------------------
__global__ __launch_bounds__(512) void k_sp(const float* __restrict__ patch,
                                            const float* __restrict__ Wv) {
    __shared__ float Aks[QN * D];
    __shared__ float us[D];
    __shared__ float qb[QN];
    __shared__ float cw_s;
    __shared__ float tile[64][65];
    int t = threadIdx.x;
    if (blockIdx.x < 256) {
        float4* As4 = reinterpret_cast<float4*>(Aks);
        const float4* g4 = reinterpret_cast<const float4*>(g_Ak);
#pragma unroll
        for (int i = 0; i < 4; i++) As4[t + i * 512] = g4[t + i * 512];
        us[t] = g_u[t];
        if (t < QN) qb[t] = g_qbk[t];
        if (t == 0) cw_s = g_cw;
        __syncthreads();

        int w = t >> 5, lane = t & 31;
        int row = blockIdx.x * 16 + w;
        const float* pr = patch + (size_t)row * D;
        float acc[QN];
        float accu = 0.f;
#pragma unroll
        for (int q = 0; q < QN; q++) acc[q] = 0.f;
#pragma unroll
        for (int c = 0; c < D / 32; c++) {
            int col = lane + c * 32;
            float pv = pr[col];
            __nv_bfloat16 h = __float2bfloat16_rn(pv);
            g_Ahi[(size_t)row * D + col] = h;
            g_Alo[(size_t)row * D + col] = __float2bfloat16_rn(pv - __bfloat162float(h));
            accu += pv * us[col];
#pragma unroll
            for (int q = 0; q < QN; q++) acc[q] += pv * Aks[q * D + col];
        }
#pragma unroll
        for (int o = 16; o; o >>= 1) accu += __shfl_xor_sync(0xffffffffu, accu, o);
        if (lane == 0) g_pf[row] = accu + cw_s;
#pragma unroll
        for (int q = 0; q < QN; q++) {
            float v = acc[q];
#pragma unroll
            for (int o = 16; o; o >>= 1) v += __shfl_xor_sync(0xffffffffu, v, o);
            if (lane == 0) g_sp[row * QN + q] = (v + qb[q]) * SCALE;
        }
    } else {
        int b = blockIdx.x - 256;
        int c0 = (b & 7) * 64, r0 = (b >> 3) * 64;
        int j = t & 63, i0 = t >> 6;
#pragma unroll
        for (int k = 0; k < 8; k++) {
            int i = i0 + k * 8;
            tile[i][j] = Wv[(size_t)(r0 + i) * D + c0 + j];
        }
        __syncthreads();
#pragma unroll
        for (int k = 0; k < 8; k++) {
            int i = i0 + k * 8;
            float v = tile[j][i];
            size_t o = (size_t)(c0 + i) * D + r0 + j;
            __nv_bfloat16 h = __float2bfloat16_rn(v);
            g_Bhi[o] = h;
            g_Blo[o] = __float2bfloat16_rn(v - __bfloat162float(h));
        }
    }
}

// ---------------------------------------------------------------------------
// k_gemm_mma: Vp = patch @ Wv + bv via mma.sync bf16 (2-term split, 3 products)
// CTA tile 128x64, 256 threads, 3-stage cp.async, 2 CTAs/SM. Plain epilogue.
// ---------------------------------------------------------------------------
#define OFF_ALO  10240
#define OFF_BHI  20480
#define OFF_BLO  25600
#define STAGE_B  30720
#define SMEM_MMA (3 * STAGE_B)

__global__ __launch_bounds__(256, 2) void k_gemm_mma(const float* __restrict__ bv) {
    extern __shared__ char sm[];
    uint32_t sbase = smem_u32(sm);
    int t = threadIdx.x, wid = t >> 5, lane = t & 31;
    int m0 = blockIdx.y * 128, n0 = blockIdx.x * 64;
    int wm = wid >> 1, wn = wid & 1;

    float acc[2][4][4];
#pragma unroll
    for (int i = 0; i < 2; i++)
#pragma unroll
        for (int j = 0; j < 4; j++)
#pragma unroll
            for (int k = 0; k < 4; k++) acc[i][j][k] = 0.f;

    int rowA[2], segA[2];
#pragma unroll
    for (int h = 0; h < 2; h++) {
        int rem = h * 256 + t;
        rowA[h] = rem >> 2; segA[h] = rem & 3;
    }
    int rowB = t >> 2, segB = t & 3;

    auto load_chunk = [&](int c) {
        int s = c % 3, k0 = c * 32;
        uint32_t base = sbase + s * STAGE_B;
#pragma unroll
        for (int h = 0; h < 2; h++) {
            int r = rowA[h], seg = segA[h];
            size_t go = (size_t)(m0 + r) * D + k0 + seg * 8;
            uint32_t so = (uint32_t)(r * 80 + seg * 16);
            cp16(base + so, g_Ahi + go);
            cp16(base + OFF_ALO + so, g_Alo + go);
        }
        {
            size_t go = (size_t)(n0 + rowB) * D + k0 + segB * 8;
            uint32_t so = (uint32_t)(rowB * 80 + segB * 16);
            cp16(base + OFF_BHI + so, g_Bhi + go);
            cp16(base + OFF_BLO + so, g_Blo + go);
        }
        CP_COMMIT();
    };

    uint32_t aoff = (uint32_t)((wm * 32 + (lane & 15)) * 80 + (lane >> 4) * 16);
    uint32_t boff = (uint32_t)((wn * 32 + (lane & 7) + ((lane >> 4) & 1) * 8) * 80
                               + ((lane >> 3) & 1) * 16);

    load_chunk(0);
    load_chunk(1);
    for (int c = 0; c < 16; c++) {
        if (c <= 13) { load_chunk(c + 2); CP_WAIT(2); }
        else if (c == 14) { CP_WAIT(1); }
        else { CP_WAIT(0); }
        __syncthreads();
        uint32_t st = sbase + (c % 3) * STAGE_B;
#pragma unroll
        for (int ks = 0; ks < 2; ks++) {
            uint32_t ah[2][4], al[2][4], bh[2][4], bl[2][4];
#pragma unroll
            for (int mt = 0; mt < 2; mt++) {
                ldm_x4(ah[mt], st + aoff + mt * (16 * 80) + ks * 32);
                ldm_x4(al[mt], st + OFF_ALO + aoff + mt * (16 * 80) + ks * 32);
            }
#pragma unroll
            for (int np = 0; np < 2; np++) {
                ldm_x4(bh[np], st + OFF_BHI + boff + np * (16 * 80) + ks * 32);
                ldm_x4(bl[np], st + OFF_BLO + boff + np * (16 * 80) + ks * 32);
            }
#pragma unroll
            for (int mt = 0; mt < 2; mt++)
#pragma unroll
                for (int np = 0; np < 2; np++) {
                    mma16816(acc[mt][2 * np],     ah[mt], &bh[np][0]);
                    mma16816(acc[mt][2 * np + 1], ah[mt], &bh[np][2]);
                    mma16816(acc[mt][2 * np],     ah[mt], &bl[np][0]);
                    mma16816(acc[mt][2 * np + 1], ah[mt], &bl[np][2]);
                    mma16816(acc[mt][2 * np],     al[mt], &bh[np][0]);
                    mma16816(acc[mt][2 * np + 1], al[mt], &bh[np][2]);
                }
        }
        __syncthreads();
    }

    int g = lane >> 2, tig = lane & 3;
#pragma unroll
    for (int mt = 0; mt < 2; mt++) {
        int r = m0 + wm * 32 + mt * 16 + g;
#pragma unroll
        for (int nt = 0; nt < 4; nt++) {
            int col = n0 + wn * 32 + nt * 8 + tig * 2;
            float b0 = __ldg(bv + col), b1 = __ldg(bv + col + 1);
            float2 v0 = make_float2(acc[mt][nt][0] + b0, acc[mt][nt][1] + b1);
            float2 v1 = make_float2(acc[mt][nt][2] + b0, acc[mt][nt][3] + b1);
            *reinterpret_cast<float2*>(&g_Vp[(size_t)r * D + col]) = v0;
            *reinterpret_cast<float2*>(&g_Vp[(size_t)(r + 8) * D + col]) = v1;
        }
    }
}

// ---------------------------------------------------------------------------
// k_weights: one block per group n, 256 threads (8 warps, 2 q each).
// Phases A-D of the collapsed combine -> es[n][64], c0[n][16].
// pf read via single gather from g_pf; __expf throughout.
// ---------------------------------------------------------------------------
__global__ __launch_bounds__(256) void k_weights(const int* __restrict__ indices,
                                                 const unsigned* __restrict__ mask,
                                                 const float* __restrict__ bf) {
    __shared__ float S[QN][72];
    __shared__ int sidx[PP];
    __shared__ float pfs[PP];
    __shared__ float tqs[QN];
    __shared__ float invq[QN];
    __shared__ float fq[QN];
    int n = blockIdx.x, t = threadIdx.x;
    int lane = t & 31, w = t >> 5;
    const float NINF = __int_as_float(0xff800000u);

    unsigned mk = 0u;
    int myidx = 0;
    if (t < PP) {
        myidx = indices[n * PP + t];
        mk = mask[n * PP + t];
        sidx[t] = myidx;
        g_sidx[n][t] = myidx;
    }
    if (t < QN) tqs[t] = g_tq[t];
    __syncthreads();

    // Phase A: 256 threads: p = t&63, q-quarter = t>>6 (4 q via one float4)
    {
        int p = t & 63, qq = t >> 6;
        int idx = sidx[p];
        unsigned pm = __shfl_sync(0xffffffffu, 0u, 0);  // placeholder no-op
        (void)pm;
        float4 v;
        if (mask[n * PP + p] != 0u) {
            v = reinterpret_cast<const float4*>(g_sp + (size_t)idx * QN)[qq];
        } else {
            v = make_float4(NINF, NINF, NINF, NINF);
        }
        int q0 = qq * 4;
        S[q0 + 0][p + 1] = v.x; S[q0 + 1][p + 1] = v.y;
        S[q0 + 2][p + 1] = v.z; S[q0 + 3][p + 1] = v.w;
        if (t < PP) pfs[t] = g_pf[myidx];
    }
    if (t < QN) S[t][0] = g_sself[t];
    __syncthreads();

    // Phase B: per-q softmax (unnorm exp kept) + fused f[q] projection
    {
        float bf0 = bf[0];
#pragma unroll
        for (int qi = 0; qi < 2; qi++) {
            int q = w * 2 + qi;
            float v0 = S[q][lane], v1 = S[q][lane + 32];
            float v2 = (lane == 0) ? S[q][64] : NINF;
            float mx = fmaxf(fmaxf(v0, v1), v2);
#pragma unroll
            for (int o = 16; o; o >>= 1) mx = fmaxf(mx, __shfl_xor_sync(0xffffffffu, mx, o));
            float e0 = __expf(v0 - mx), e1 = __expf(v1 - mx);
            float e2 = (lane == 0) ? __expf(v2 - mx) : 0.f;
            float s = e0 + e1 + e2;
#pragma unroll
            for (int o = 16; o; o >>= 1) s += __shfl_xor_sync(0xffffffffu, s, o);
            S[q][lane] = e0; S[q][lane + 32] = e1;
            if (lane == 0) S[q][64] = e2;
            float pr0 = (lane == 0) ? tqs[q] : pfs[lane - 1];
            float fp = e0 * pr0 + e1 * pfs[lane + 31];
            if (lane == 0) fp += e2 * pfs[63];
#pragma unroll
            for (int o = 16; o; o >>= 1) fp += __shfl_xor_sync(0xffffffffu, fp, o);
            if (lane == 0) {
                invq[q] = 1.f / s;
                fq[q] = fp / s + bf0;
            }
        }
    }
    __syncthreads();

    // Phase C: fusion softmax over q (redundant per thread)
    float c[QN];
    {
        float fv[QN], mx = -3.4e38f;
#pragma unroll
        for (int q = 0; q < QN; q++) { fv[q] = fq[q]; mx = fmaxf(mx, fv[q]); }
        float s = 0.f;
#pragma unroll
        for (int q = 0; q < QN; q++) { fv[q] = __expf(fv[q] - mx); s += fv[q]; }
        float inv = 1.f / s;
#pragma unroll
        for (int q = 0; q < QN; q++) c[q] = fv[q] * inv * invq[q];
    }

    // Phase D: outputs
    if (t < PP) {
        float ep = 0.f;
#pragma unroll
        for (int q = 0; q < QN; q++) ep += c[q] * S[q][t + 1];
        g_es[n][t] = ep;
    }
    if (t < QN) g_c0[n][t] = c[t] * S[t][0];
}

// ---------------------------------------------------------------------------
// k_gather: one block per group n, 256 threads (2 p-halves x 128 cols).
// Pure streaming: out[d] = sum_q c0*VQ + sum_p es[p]*Vp[idx_p,d].
// ---------------------------------------------------------------------------
__global__ __launch_bounds__(256) void k_gather(float* __restrict__ out) {
    __shared__ __align__(16) float4 part[128];
    __shared__ float esb[PP];
    __shared__ float c0b[QN];
    __shared__ int sidx[PP];
    int n = blockIdx.x, t = threadIdx.x;

    if (t < PP) { esb[t] = g_es[n][t]; sidx[t] = g_sidx[n][t]; }
    if (t < QN) c0b[t] = g_c0[n][t];
    __syncthreads();

    int tl = t & 127, half = t >> 7;
    float4 o = make_float4(0.f, 0.f, 0.f, 0.f);
    if (half == 0) {
        const float4* VQ4 = reinterpret_cast<const float4*>(g_VQ);
#pragma unroll
        for (int q = 0; q < QN; q++) {
            float c0 = c0b[q];
            float4 vq = VQ4[q * 128 + tl];
            o.x += c0 * vq.x; o.y += c0 * vq.y;
            o.z += c0 * vq.z; o.w += c0 * vq.w;
        }
    }
    const float4* Vp4 = reinterpret_cast<const float4*>(g_Vp);
#pragma unroll 8
    for (int pi = 0; pi < 32; pi++) {
        int p = half * 32 + pi;
        float4 v = Vp4[(size_t)sidx[p] * 128 + tl];
        float ep = esb[p];
        o.x += ep * v.x; o.y += ep * v.y;
        o.z += ep * v.z; o.w += ep * v.w;
    }
    if (half == 1) part[tl] = o;
    __syncthreads();
    if (half == 0) {
        float4 p1 = part[tl];
        o.x += p1.x; o.y += p1.y; o.z += p1.z; o.w += p1.w;
        reinterpret_cast<float4*>(out)[(size_t)n * 128 + tl] = o;
    }
}

// ---------------------------------------------------------------------------
extern "C" void kernel_launch(void* const* d_in, const int* in_sizes, int n_in,
                              void* d_out, int out_size) {
    (void)in_sizes; (void)n_in; (void)out_size;
    const float* patch   = (const float*)d_in[0];
    const float* query   = (const float*)d_in[1];
    const float* Wk      = (const float*)d_in[2];
    const float* bk      = (const float*)d_in[3];
    const float* Wv      = (const float*)d_in[4];
    const float* bv      = (const float*)d_in[5];
    const float* Wf      = (const float*)d_in[6];
    const float* bf      = (const float*)d_in[7];
    const int* indices   = (const int*)d_in[8];
    const unsigned* mask = (const unsigned*)d_in[9];
    float* out           = (float*)d_out;

    cudaFuncSetAttribute(k_gemm_mma, cudaFuncAttributeMaxDynamicSharedMemorySize, SMEM_MMA);

    k_pre<<<dim3(QN, 3), D>>>(query, Wk, Wv, bv, bk, Wf);
    k_sp<<<256 + 64, 512>>>(patch, Wv);
    k_gemm_mma<<<dim3(8, 32), 256, SMEM_MMA>>>(bv);
    k_weights<<<NG, 256>>>(indices, mask, bf);
    k_gather<<<NG, 256>>>(out);
}

// round 15
// speedup vs baseline: 1.0704x; 1.0704x over previous
#include <cuda_runtime.h>
#include <cuda_bf16.h>
#include <math.h>
#include <stdint.h>

// Problem constants
#define D   512
#define QN  16
#define NT  4096   // B*L tokens
#define NG  512    // N gathered groups
#define PP  64     // group size P

#define SCALE 0.04419417382415922f  // 1/sqrt(512)

// Scratch (allocation-free: __device__ globals)
__device__ float g_Vp[NT * D];            // patch @ Wv + bv      [4096,512]
__device__ __nv_bfloat16 g_Ahi[NT * D];   // bf16 hi split of patch
__device__ __nv_bfloat16 g_Alo[NT * D];   // bf16 lo split of patch
__device__ __nv_bfloat16 g_Bhi[D * D];    // bf16 hi split of Wv^T ([n][k])
__device__ __nv_bfloat16 g_Blo[D * D];    // bf16 lo split of Wv^T
__device__ float g_sp[NT * QN];           // scaled patch scores  [4096,16]
__device__ float g_VQ[QN * D];            // Q0 @ Wv + bv         [16,512]
__device__ float g_Ak[QN * D];            // (Wk @ Q0^T)^T        [16,512]
__device__ float g_pf[NT];                // pf[t] = patch[t].u + cw (== Vp.Wf)
__device__ float g_u[D];                  // Wv @ Wf              [512]
__device__ float g_cw;                    // bv . Wf
__device__ float g_tq[QN];                // VQ @ Wf              [16]
__device__ float g_sself[QN];             // self-token scores    [16]
__device__ float g_qbk[QN];               // Q0[q] . bk           [16]
__device__ float g_es[NG][PP];            // effective gather weights
__device__ float g_c0[NG][QN];            // VQ-term coefficients
__device__ int   g_sidx[NG][PP];          // cached indices

// ---- PTX helpers (all sm_80-level, valid for compute_103 target) -----------
__device__ __forceinline__ uint32_t smem_u32(const void* p) {
    uint32_t a;
    asm("{ .reg .u64 tmp; cvta.to.shared.u64 tmp, %1; cvt.u32.u64 %0, tmp; }"
        : "=r"(a) : "l"(p));
    return a;
}
__device__ __forceinline__ void cp16(uint32_t sdst, const void* gsrc) {
    asm volatile("cp.async.cg.shared.global [%0], [%1], 16;"
                 :: "r"(sdst), "l"(gsrc) : "memory");
}
#define CP_COMMIT() asm volatile("cp.async.commit_group;" ::: "memory")
#define CP_WAIT(n)  asm volatile("cp.async.wait_group %0;" :: "n"(n) : "memory")

__device__ __forceinline__ void ldm_x4(uint32_t* r, uint32_t addr) {
    asm volatile("ldmatrix.sync.aligned.m8n8.x4.shared.b16 {%0,%1,%2,%3}, [%4];"
                 : "=r"(r[0]), "=r"(r[1]), "=r"(r[2]), "=r"(r[3]) : "r"(addr));
}
__device__ __forceinline__ void mma16816(float* c, const uint32_t* a, const uint32_t* b) {
    asm volatile("mma.sync.aligned.m16n8k16.row.col.f32.bf16.bf16.f32 "
                 "{%0,%1,%2,%3}, {%4,%5,%6,%7}, {%8,%9}, {%0,%1,%2,%3};"
                 : "+f"(c[0]), "+f"(c[1]), "+f"(c[2]), "+f"(c[3])
                 : "r"(a[0]), "r"(a[1]), "r"(a[2]), "r"(a[3]), "r"(b[0]), "r"(b[1]));
}

// ---------------------------------------------------------------------------
// k_pre: grid (16, 3), block 512.
//  y==0: VQ[q] (float4 col-groups) + tq[q]
//  y==1: Ak[q][t] + qbk / sself reductions
//  y==2: u = Wv @ Wf (block x -> 32 rows) ; block x==0 also cw = bv.Wf
// ---------------------------------------------------------------------------
__global__ void k_pre(const float* __restrict__ query, const float* __restrict__ Wk,
                      const float* __restrict__ Wv, const float* __restrict__ bv,
                      const float* __restrict__ bk, const float* __restrict__ Wf) {
    __shared__ float q0[D];
    __shared__ float red[2][16];
    __shared__ __align__(16) float4 part4[4][128];
    int q = blockIdx.x, t = threadIdx.x;
    int w = t >> 5, lane = t & 31;

    if (blockIdx.y == 2) {
        q0[t] = Wf[t];
        __syncthreads();
#pragma unroll
        for (int hh = 0; hh < 2; hh++) {
            int r = blockIdx.x * 32 + hh * 16 + w;
            const float* row = Wv + (size_t)r * D;
            float s = 0.f;
#pragma unroll
            for (int i = 0; i < D / 32; i++) s += row[lane + i * 32] * q0[lane + i * 32];
#pragma unroll
            for (int o = 16; o; o >>= 1) s += __shfl_xor_sync(0xffffffffu, s, o);
            if (lane == 0) g_u[r] = s;
        }
        if (blockIdx.x == 0) {
            float r1 = bv[t] * q0[t];
#pragma unroll
            for (int o = 16; o; o >>= 1) r1 += __shfl_xor_sync(0xffffffffu, r1, o);
            if (lane == 0) red[0][w] = r1;
            __syncthreads();
            if (t == 0) {
                float s = 0.f;
#pragma unroll
                for (int i = 0; i < 16; i++) s += red[0][i];
                g_cw = s;
            }
        }
        return;
    }

    q0[t] = query[q * D + t];
    __syncthreads();

    if (blockIdx.y == 0) {
        int cg = t & 127, rc = t >> 7;
        const float4* Wv4 = reinterpret_cast<const float4*>(Wv);
        float4 a = make_float4(0.f, 0.f, 0.f, 0.f);
#pragma unroll 8
        for (int i = 0; i < 128; i++) {
            int d = rc * 128 + i;
            float qd = q0[d];
            float4 wv = Wv4[(size_t)d * 128 + cg];
            a.x += qd * wv.x; a.y += qd * wv.y;
            a.z += qd * wv.z; a.w += qd * wv.w;
        }
        part4[rc][cg] = a;
        __syncthreads();
        float tqv = 0.f;
        if (t < 128) {
            float4 r = part4[0][t], p1 = part4[1][t], p2 = part4[2][t], p3 = part4[3][t];
            float4 bv4 = reinterpret_cast<const float4*>(bv)[t];
            r.x += p1.x + p2.x + p3.x + bv4.x;
            r.y += p1.y + p2.y + p3.y + bv4.y;
            r.z += p1.z + p2.z + p3.z + bv4.z;
            r.w += p1.w + p2.w + p3.w + bv4.w;
            reinterpret_cast<float4*>(g_VQ)[q * 128 + t] = r;
            float4 wf = reinterpret_cast<const float4*>(Wf)[t];
            tqv = r.x * wf.x + r.y * wf.y + r.z * wf.z + r.w * wf.w;
        }
#pragma unroll
        for (int o = 16; o; o >>= 1) tqv += __shfl_xor_sync(0xffffffffu, tqv, o);
        if (lane == 0 && w < 4) red[0][w] = tqv;
        __syncthreads();
        if (t == 0) g_tq[q] = red[0][0] + red[0][1] + red[0][2] + red[0][3];
    } else {
        const float4* wr = reinterpret_cast<const float4*>(Wk + (size_t)t * D);
        float a0 = 0.f, a1 = 0.f;
#pragma unroll 8
        for (int i = 0; i < D / 8; i++) {
            float4 w0 = wr[2 * i], w1 = wr[2 * i + 1];
            a0 += w0.x * q0[8*i+0] + w0.y * q0[8*i+1] + w0.z * q0[8*i+2] + w0.w * q0[8*i+3];
            a1 += w1.x * q0[8*i+4] + w1.y * q0[8*i+5] + w1.z * q0[8*i+6] + w1.w * q0[8*i+7];
        }
        float r = a0 + a1;
        g_Ak[q * D + t] = r;
        float r0v = q0[t] * r;
        float r1v = q0[t] * bk[t];
#pragma unroll
        for (int o = 16; o; o >>= 1) {
            r0v += __shfl_xor_sync(0xffffffffu, r0v, o);
            r1v += __shfl_xor_sync(0xffffffffu, r1v, o);
        }
        if (lane == 0) { red[0][w] = r0v; red[1][w] = r1v; }
        __syncthreads();
        if (w == 0) {
            float x0 = (lane < 16) ? red[0][lane] : 0.f;
            float x1 = (lane < 16) ? red[1][lane] : 0.f;
#pragma unroll
            for (int o = 8; o; o >>= 1) {
                x0 += __shfl_xor_sync(0xffffffffu, x0, o);
                x1 += __shfl_xor_sync(0xffffffffu, x1, o);
            }
            if (lane == 0) {
                g_qbk[q] = x1;
                g_sself[q] = (x0 + x1) * SCALE;
            }
        }
    }
}

// ---------------------------------------------------------------------------
// k_sp: fused. Blocks 0..255: sp scores + pf (17th accumulator) + bf16 splits
// for 16 token rows. Blocks 256..319: Wv transpose/split.
// ---------------------------------------------------------------------------
__global__ __launch_bounds__(512) void k_sp(const float* __restrict__ patch,
                                            const float* __restrict__ Wv) {
    __shared__ float Aks[QN * D];
    __shared__ float us[D];
    __shared__ float qb[QN];
    __shared__ float cw_s;
    __shared__ float tile[64][65];
    int t = threadIdx.x;
    if (blockIdx.x < 256) {
        float4* As4 = reinterpret_cast<float4*>(Aks);
        const float4* g4 = reinterpret_cast<const float4*>(g_Ak);
#pragma unroll
        for (int i = 0; i < 4; i++) As4[t + i * 512] = g4[t + i * 512];
        us[t] = g_u[t];
        if (t < QN) qb[t] = g_qbk[t];
        if (t == 0) cw_s = g_cw;
        __syncthreads();

        int w = t >> 5, lane = t & 31;
        int row = blockIdx.x * 16 + w;
        const float* pr = patch + (size_t)row * D;
        float acc[QN];
        float accu = 0.f;
#pragma unroll
        for (int q = 0; q < QN; q++) acc[q] = 0.f;
#pragma unroll
        for (int c = 0; c < D / 32; c++) {
            int col = lane + c * 32;
            float pv = pr[col];
            __nv_bfloat16 h = __float2bfloat16_rn(pv);
            g_Ahi[(size_t)row * D + col] = h;
            g_Alo[(size_t)row * D + col] = __float2bfloat16_rn(pv - __bfloat162float(h));
            accu += pv * us[col];
#pragma unroll
            for (int q = 0; q < QN; q++) acc[q] += pv * Aks[q * D + col];
        }
#pragma unroll
        for (int o = 16; o; o >>= 1) accu += __shfl_xor_sync(0xffffffffu, accu, o);
        if (lane == 0) g_pf[row] = accu + cw_s;
#pragma unroll
        for (int q = 0; q < QN; q++) {
            float v = acc[q];
#pragma unroll
            for (int o = 16; o; o >>= 1) v += __shfl_xor_sync(0xffffffffu, v, o);
            if (lane == 0) g_sp[row * QN + q] = (v + qb[q]) * SCALE;
        }
    } else {
        int b = blockIdx.x - 256;
        int c0 = (b & 7) * 64, r0 = (b >> 3) * 64;
        int j = t & 63, i0 = t >> 6;
#pragma unroll
        for (int k = 0; k < 8; k++) {
            int i = i0 + k * 8;
            tile[i][j] = Wv[(size_t)(r0 + i) * D + c0 + j];
        }
        __syncthreads();
#pragma unroll
        for (int k = 0; k < 8; k++) {
            int i = i0 + k * 8;
            float v = tile[j][i];
            size_t o = (size_t)(c0 + i) * D + r0 + j;
            __nv_bfloat16 h = __float2bfloat16_rn(v);
            g_Bhi[o] = h;
            g_Blo[o] = __float2bfloat16_rn(v - __bfloat162float(h));
        }
    }
}

// ---------------------------------------------------------------------------
// k_gemm_mma: Vp = patch @ Wv + bv via mma.sync bf16 (2-term split, 3 products)
// CTA tile 128x64, 256 threads, 3-stage cp.async, 2 CTAs/SM. Plain epilogue.
// ---------------------------------------------------------------------------
#define OFF_ALO  10240
#define OFF_BHI  20480
#define OFF_BLO  25600
#define STAGE_B  30720
#define SMEM_MMA (3 * STAGE_B)

__global__ __launch_bounds__(256, 2) void k_gemm_mma(const float* __restrict__ bv) {
    extern __shared__ char sm[];
    uint32_t sbase = smem_u32(sm);
    int t = threadIdx.x, wid = t >> 5, lane = t & 31;
    int m0 = blockIdx.y * 128, n0 = blockIdx.x * 64;
    int wm = wid >> 1, wn = wid & 1;

    float acc[2][4][4];
#pragma unroll
    for (int i = 0; i < 2; i++)
#pragma unroll
        for (int j = 0; j < 4; j++)
#pragma unroll
            for (int k = 0; k < 4; k++) acc[i][j][k] = 0.f;

    int rowA[2], segA[2];
#pragma unroll
    for (int h = 0; h < 2; h++) {
        int rem = h * 256 + t;
        rowA[h] = rem >> 2; segA[h] = rem & 3;
    }
    int rowB = t >> 2, segB = t & 3;

    auto load_chunk = [&](int c) {
        int s = c % 3, k0 = c * 32;
        uint32_t base = sbase + s * STAGE_B;
#pragma unroll
        for (int h = 0; h < 2; h++) {
            int r = rowA[h], seg = segA[h];
            size_t go = (size_t)(m0 + r) * D + k0 + seg * 8;
            uint32_t so = (uint32_t)(r * 80 + seg * 16);
            cp16(base + so, g_Ahi + go);
            cp16(base + OFF_ALO + so, g_Alo + go);
        }
        {
            size_t go = (size_t)(n0 + rowB) * D + k0 + segB * 8;
            uint32_t so = (uint32_t)(rowB * 80 + segB * 16);
            cp16(base + OFF_BHI + so, g_Bhi + go);
            cp16(base + OFF_BLO + so, g_Blo + go);
        }
        CP_COMMIT();
    };

    uint32_t aoff = (uint32_t)((wm * 32 + (lane & 15)) * 80 + (lane >> 4) * 16);
    uint32_t boff = (uint32_t)((wn * 32 + (lane & 7) + ((lane >> 4) & 1) * 8) * 80
                               + ((lane >> 3) & 1) * 16);

    load_chunk(0);
    load_chunk(1);
    for (int c = 0; c < 16; c++) {
        if (c <= 13) { load_chunk(c + 2); CP_WAIT(2); }
        else if (c == 14) { CP_WAIT(1); }
        else { CP_WAIT(0); }
        __syncthreads();
        uint32_t st = sbase + (c % 3) * STAGE_B;
#pragma unroll
        for (int ks = 0; ks < 2; ks++) {
            uint32_t ah[2][4], al[2][4], bh[2][4], bl[2][4];
#pragma unroll
            for (int mt = 0; mt < 2; mt++) {
                ldm_x4(ah[mt], st + aoff + mt * (16 * 80) + ks * 32);
                ldm_x4(al[mt], st + OFF_ALO + aoff + mt * (16 * 80) + ks * 32);
            }
#pragma unroll
            for (int np = 0; np < 2; np++) {
                ldm_x4(bh[np], st + OFF_BHI + boff + np * (16 * 80) + ks * 32);
                ldm_x4(bl[np], st + OFF_BLO + boff + np * (16 * 80) + ks * 32);
            }
#pragma unroll
            for (int mt = 0; mt < 2; mt++)
#pragma unroll
                for (int np = 0; np < 2; np++) {
                    mma16816(acc[mt][2 * np],     ah[mt], &bh[np][0]);
                    mma16816(acc[mt][2 * np + 1], ah[mt], &bh[np][2]);
                    mma16816(acc[mt][2 * np],     ah[mt], &bl[np][0]);
                    mma16816(acc[mt][2 * np + 1], ah[mt], &bl[np][2]);
                    mma16816(acc[mt][2 * np],     al[mt], &bh[np][0]);
                    mma16816(acc[mt][2 * np + 1], al[mt], &bh[np][2]);
                }
        }
        __syncthreads();
    }

    int g = lane >> 2, tig = lane & 3;
#pragma unroll
    for (int mt = 0; mt < 2; mt++) {
        int r = m0 + wm * 32 + mt * 16 + g;
#pragma unroll
        for (int nt = 0; nt < 4; nt++) {
            int col = n0 + wn * 32 + nt * 8 + tig * 2;
            float b0 = __ldg(bv + col), b1 = __ldg(bv + col + 1);
            float2 v0 = make_float2(acc[mt][nt][0] + b0, acc[mt][nt][1] + b1);
            float2 v1 = make_float2(acc[mt][nt][2] + b0, acc[mt][nt][3] + b1);
            *reinterpret_cast<float2*>(&g_Vp[(size_t)r * D + col]) = v0;
            *reinterpret_cast<float2*>(&g_Vp[(size_t)(r + 8) * D + col]) = v1;
        }
    }
}

// ---------------------------------------------------------------------------
// k_weights: one block per group n, 256 threads (8 warps, 2 q each).
// Phases A-D of the collapsed combine -> es[n][64], c0[n][16].
// Independent of the GEMM (pf comes from k_sp) -> runs on a forked stream
// concurrently with k_gemm_mma.
// ---------------------------------------------------------------------------
__global__ __launch_bounds__(256) void k_weights(const int* __restrict__ indices,
                                                 const unsigned* __restrict__ mask,
                                                 const float* __restrict__ bf) {
    __shared__ float S[QN][72];
    __shared__ int sidx[PP];
    __shared__ float pfs[PP];
    __shared__ float tqs[QN];
    __shared__ float invq[QN];
    __shared__ float fq[QN];
    int n = blockIdx.x, t = threadIdx.x;
    int lane = t & 31, w = t >> 5;
    const float NINF = __int_as_float(0xff800000u);

    int myidx = 0;
    if (t < PP) {
        myidx = indices[n * PP + t];
        sidx[t] = myidx;
        g_sidx[n][t] = myidx;
    }
    if (t < QN) tqs[t] = g_tq[t];
    __syncthreads();

    // Phase A: 256 threads: p = t&63, q-quarter = t>>6 (4 q via one float4)
    {
        int p = t & 63, qq = t >> 6;
        int idx = sidx[p];
        float4 v;
        if (mask[n * PP + p] != 0u) {
            v = reinterpret_cast<const float4*>(g_sp + (size_t)idx * QN)[qq];
        } else {
            v = make_float4(NINF, NINF, NINF, NINF);
        }
        int q0 = qq * 4;
        S[q0 + 0][p + 1] = v.x; S[q0 + 1][p + 1] = v.y;
        S[q0 + 2][p + 1] = v.z; S[q0 + 3][p + 1] = v.w;
        if (t < PP) pfs[t] = g_pf[myidx];
    }
    if (t < QN) S[t][0] = g_sself[t];
    __syncthreads();

    // Phase B: per-q softmax (unnorm exp kept) + fused f[q] projection
    {
        float bf0 = bf[0];
#pragma unroll
        for (int qi = 0; qi < 2; qi++) {
            int q = w * 2 + qi;
            float v0 = S[q][lane], v1 = S[q][lane + 32];
            float v2 = (lane == 0) ? S[q][64] : NINF;
            float mx = fmaxf(fmaxf(v0, v1), v2);
#pragma unroll
            for (int o = 16; o; o >>= 1) mx = fmaxf(mx, __shfl_xor_sync(0xffffffffu, mx, o));
            float e0 = __expf(v0 - mx), e1 = __expf(v1 - mx);
            float e2 = (lane == 0) ? __expf(v2 - mx) : 0.f;
            float s = e0 + e1 + e2;
#pragma unroll
            for (int o = 16; o; o >>= 1) s += __shfl_xor_sync(0xffffffffu, s, o);
            S[q][lane] = e0; S[q][lane + 32] = e1;
            if (lane == 0) S[q][64] = e2;
            float pr0 = (lane == 0) ? tqs[q] : pfs[lane - 1];
            float fp = e0 * pr0 + e1 * pfs[lane + 31];
            if (lane == 0) fp += e2 * pfs[63];
#pragma unroll
            for (int o = 16; o; o >>= 1) fp += __shfl_xor_sync(0xffffffffu, fp, o);
            if (lane == 0) {
                invq[q] = 1.f / s;
                fq[q] = fp / s + bf0;
            }
        }
    }
    __syncthreads();

    // Phase C: fusion softmax over q (redundant per thread)
    float c[QN];
    {
        float fv[QN], mx = -3.4e38f;
#pragma unroll
        for (int q = 0; q < QN; q++) { fv[q] = fq[q]; mx = fmaxf(mx, fv[q]); }
        float s = 0.f;
#pragma unroll
        for (int q = 0; q < QN; q++) { fv[q] = __expf(fv[q] - mx); s += fv[q]; }
        float inv = 1.f / s;
#pragma unroll
        for (int q = 0; q < QN; q++) c[q] = fv[q] * inv * invq[q];
    }

    // Phase D: outputs
    if (t < PP) {
        float ep = 0.f;
#pragma unroll
        for (int q = 0; q < QN; q++) ep += c[q] * S[q][t + 1];
        g_es[n][t] = ep;
    }
    if (t < QN) g_c0[n][t] = c[t] * S[t][0];
}

// ---------------------------------------------------------------------------
// k_gather: one block per group n, 256 threads (2 p-halves x 128 cols).
// Pure streaming: out[d] = sum_q c0*VQ + sum_p es[p]*Vp[idx_p,d].
// ---------------------------------------------------------------------------
__global__ __launch_bounds__(256) void k_gather(float* __restrict__ out) {
    __shared__ __align__(16) float4 part[128];
    __shared__ float esb[PP];
    __shared__ float c0b[QN];
    __shared__ int sidx[PP];
    int n = blockIdx.x, t = threadIdx.x;

    if (t < PP) { esb[t] = g_es[n][t]; sidx[t] = g_sidx[n][t]; }
    if (t < QN) c0b[t] = g_c0[n][t];
    __syncthreads();

    int tl = t & 127, half = t >> 7;
    float4 o = make_float4(0.f, 0.f, 0.f, 0.f);
    if (half == 0) {
        const float4* VQ4 = reinterpret_cast<const float4*>(g_VQ);
#pragma unroll
        for (int q = 0; q < QN; q++) {
            float c0 = c0b[q];
            float4 vq = VQ4[q * 128 + tl];
            o.x += c0 * vq.x; o.y += c0 * vq.y;
            o.z += c0 * vq.z; o.w += c0 * vq.w;
        }
    }
    const float4* Vp4 = reinterpret_cast<const float4*>(g_Vp);
#pragma unroll 8
    for (int pi = 0; pi < 32; pi++) {
        int p = half * 32 + pi;
        float4 v = Vp4[(size_t)sidx[p] * 128 + tl];
        float ep = esb[p];
        o.x += ep * v.x; o.y += ep * v.y;
        o.z += ep * v.z; o.w += ep * v.w;
    }
    if (half == 1) part[tl] = o;
    __syncthreads();
    if (half == 0) {
        float4 p1 = part[tl];
        o.x += p1.x; o.y += p1.y; o.z += p1.z; o.w += p1.w;
        reinterpret_cast<float4*>(out)[(size_t)n * 128 + tl] = o;
    }
}

// ---------------------------------------------------------------------------
extern "C" void kernel_launch(void* const* d_in, const int* in_sizes, int n_in,
                              void* d_out, int out_size) {
    (void)in_sizes; (void)n_in; (void)out_size;
    const float* patch   = (const float*)d_in[0];
    const float* query   = (const float*)d_in[1];
    const float* Wk      = (const float*)d_in[2];
    const float* bk      = (const float*)d_in[3];
    const float* Wv      = (const float*)d_in[4];
    const float* bv      = (const float*)d_in[5];
    const float* Wf      = (const float*)d_in[6];
    const float* bf      = (const float*)d_in[7];
    const int* indices   = (const int*)d_in[8];
    const unsigned* mask = (const unsigned*)d_in[9];
    float* out           = (float*)d_out;

    // One-time host-side resources (no device memory involved).
    static cudaStream_t s2 = nullptr;
    static cudaEvent_t evFork = nullptr, evJoin = nullptr;
    if (s2 == nullptr) {
        cudaStreamCreateWithFlags(&s2, cudaStreamNonBlocking);
        cudaEventCreateWithFlags(&evFork, cudaEventDisableTiming);
        cudaEventCreateWithFlags(&evJoin, cudaEventDisableTiming);
        cudaFuncSetAttribute(k_gemm_mma, cudaFuncAttributeMaxDynamicSharedMemorySize, SMEM_MMA);
    }

    k_pre<<<dim3(QN, 3), D>>>(query, Wk, Wv, bv, bk, Wf);
    k_sp<<<256 + 64, 512>>>(patch, Wv);

    // Fork: k_weights (depends only on k_sp outputs) runs concurrently with
    // the GEMM on a side stream; join before k_gather.
    cudaEventRecord(evFork, 0);
    cudaStreamWaitEvent(s2, evFork, 0);
    k_weights<<<NG, 256, 0, s2>>>(indices, mask, bf);
    cudaEventRecord(evJoin, s2);

    k_gemm_mma<<<dim3(8, 32), 256, SMEM_MMA>>>(bv);

    cudaStreamWaitEvent(0, evJoin, 0);
    k_gather<<<NG, 256>>>(out);
}

// round 16
// speedup vs baseline: 1.3494x; 1.2607x over previous
#include <cuda_runtime.h>
#include <cuda_bf16.h>
#include <math.h>
#include <stdint.h>

// Problem constants
#define D   512
#define QN  16
#define NT  4096   // B*L tokens
#define NG  512    // N gathered groups
#define PP  64     // group size P

#define SCALE 0.04419417382415922f  // 1/sqrt(512)

// Scratch (allocation-free: __device__ globals)
__device__ float g_Vp[NT * D];            // patch @ Wv + bv      [4096,512]
__device__ __nv_bfloat16 g_Ahi[NT * D];   // bf16 hi split of patch
__device__ __nv_bfloat16 g_Alo[NT * D];   // bf16 lo split of patch
__device__ __nv_bfloat16 g_Bhi[D * D];    // bf16 hi split of Wv^T ([n][k])
__device__ __nv_bfloat16 g_Blo[D * D];    // bf16 lo split of Wv^T
__device__ float g_sp[NT * QN];           // scaled patch scores  [4096,16]
__device__ float g_VQ[QN * D];            // Q0 @ Wv + bv         [16,512]
__device__ float g_Ak[QN * D];            // (Wk @ Q0^T)^T        [16,512]
__device__ float g_pf[NT];                // pf[t] = patch[t].u + cw (== Vp.Wf)
__device__ float g_u[D];                  // Wv @ Wf              [512]
__device__ float g_cw;                    // bv . Wf
__device__ float g_tq[QN];                // VQ @ Wf              [16]
__device__ float g_sself[QN];             // self-token scores    [16]
__device__ float g_qbk[QN];               // Q0[q] . bk           [16]
__device__ float g_es[NG][PP];            // effective gather weights
__device__ float g_c0[NG][QN];            // VQ-term coefficients
__device__ int   g_sidx[NG][PP];          // cached indices

// ---- PTX helpers (all sm_80-level, valid for compute_103 target) -----------
__device__ __forceinline__ uint32_t smem_u32(const void* p) {
    uint32_t a;
    asm("{ .reg .u64 tmp; cvta.to.shared.u64 tmp, %1; cvt.u32.u64 %0, tmp; }"
        : "=r"(a) : "l"(p));
    return a;
}
__device__ __forceinline__ void cp16(uint32_t sdst, const void* gsrc) {
    asm volatile("cp.async.cg.shared.global [%0], [%1], 16;"
                 :: "r"(sdst), "l"(gsrc) : "memory");
}
#define CP_COMMIT() asm volatile("cp.async.commit_group;" ::: "memory")
#define CP_WAIT(n)  asm volatile("cp.async.wait_group %0;" :: "n"(n) : "memory")

__device__ __forceinline__ void ldm_x4(uint32_t* r, uint32_t addr) {
    asm volatile("ldmatrix.sync.aligned.m8n8.x4.shared.b16 {%0,%1,%2,%3}, [%4];"
                 : "=r"(r[0]), "=r"(r[1]), "=r"(r[2]), "=r"(r[3]) : "r"(addr));
}
__device__ __forceinline__ void mma16816(float* c, const uint32_t* a, const uint32_t* b) {
    asm volatile("mma.sync.aligned.m16n8k16.row.col.f32.bf16.bf16.f32 "
                 "{%0,%1,%2,%3}, {%4,%5,%6,%7}, {%8,%9}, {%0,%1,%2,%3};"
                 : "+f"(c[0]), "+f"(c[1]), "+f"(c[2]), "+f"(c[3])
                 : "r"(a[0]), "r"(a[1]), "r"(a[2]), "r"(a[3]), "r"(b[0]), "r"(b[1]));
}

// ---------------------------------------------------------------------------
// k_split (side stream): blocks 0..2047: bf16 hi/lo split of patch (float4
// per thread). Blocks 2048..2111: Wv transpose + bf16 hi/lo splits.
// Depends ONLY on inputs -> runs concurrently with k_pre.
// ---------------------------------------------------------------------------
__global__ __launch_bounds__(256) void k_split(const float* __restrict__ patch,
                                               const float* __restrict__ Wv) {
    if (blockIdx.x < 2048) {
        int i = blockIdx.x * 256 + threadIdx.x;
        float4 v = reinterpret_cast<const float4*>(patch)[i];
        __nv_bfloat162 h0, h1, l0, l1;
        h0.x = __float2bfloat16_rn(v.x); l0.x = __float2bfloat16_rn(v.x - __bfloat162float(h0.x));
        h0.y = __float2bfloat16_rn(v.y); l0.y = __float2bfloat16_rn(v.y - __bfloat162float(h0.y));
        h1.x = __float2bfloat16_rn(v.z); l1.x = __float2bfloat16_rn(v.z - __bfloat162float(h1.x));
        h1.y = __float2bfloat16_rn(v.w); l1.y = __float2bfloat16_rn(v.w - __bfloat162float(h1.y));
        reinterpret_cast<__nv_bfloat162*>(g_Ahi)[2 * i]     = h0;
        reinterpret_cast<__nv_bfloat162*>(g_Ahi)[2 * i + 1] = h1;
        reinterpret_cast<__nv_bfloat162*>(g_Alo)[2 * i]     = l0;
        reinterpret_cast<__nv_bfloat162*>(g_Alo)[2 * i + 1] = l1;
    } else {
        __shared__ float tile[64][65];
        int b = blockIdx.x - 2048;
        int c0 = (b & 7) * 64, r0 = (b >> 3) * 64;
        int j = threadIdx.x & 63, i0 = threadIdx.x >> 6;
#pragma unroll
        for (int k = 0; k < 16; k++) {
            int i = i0 + k * 4;
            tile[i][j] = Wv[(size_t)(r0 + i) * D + c0 + j];
        }
        __syncthreads();
#pragma unroll
        for (int k = 0; k < 16; k++) {
            int i = i0 + k * 4;
            float v = tile[j][i];
            size_t o = (size_t)(c0 + i) * D + r0 + j;
            __nv_bfloat16 h = __float2bfloat16_rn(v);
            g_Bhi[o] = h;
            g_Blo[o] = __float2bfloat16_rn(v - __bfloat162float(h));
        }
    }
}

// ---------------------------------------------------------------------------
// k_pre: grid (16, 3), block 512.
//  y==0: VQ[q] + tq[q];  y==1: Ak[q] + qbk/sself;  y==2: u = Wv@Wf, cw = bv.Wf
// ---------------------------------------------------------------------------
__global__ void k_pre(const float* __restrict__ query, const float* __restrict__ Wk,
                      const float* __restrict__ Wv, const float* __restrict__ bv,
                      const float* __restrict__ bk, const float* __restrict__ Wf) {
    __shared__ float q0[D];
    __shared__ float red[2][16];
    __shared__ __align__(16) float4 part4[4][128];
    int q = blockIdx.x, t = threadIdx.x;
    int w = t >> 5, lane = t & 31;

    if (blockIdx.y == 2) {
        q0[t] = Wf[t];
        __syncthreads();
#pragma unroll
        for (int hh = 0; hh < 2; hh++) {
            int r = blockIdx.x * 32 + hh * 16 + w;
            const float* row = Wv + (size_t)r * D;
            float s = 0.f;
#pragma unroll
            for (int i = 0; i < D / 32; i++) s += row[lane + i * 32] * q0[lane + i * 32];
#pragma unroll
            for (int o = 16; o; o >>= 1) s += __shfl_xor_sync(0xffffffffu, s, o);
            if (lane == 0) g_u[r] = s;
        }
        if (blockIdx.x == 0) {
            float r1 = bv[t] * q0[t];
#pragma unroll
            for (int o = 16; o; o >>= 1) r1 += __shfl_xor_sync(0xffffffffu, r1, o);
            if (lane == 0) red[0][w] = r1;
            __syncthreads();
            if (t == 0) {
                float s = 0.f;
#pragma unroll
                for (int i = 0; i < 16; i++) s += red[0][i];
                g_cw = s;
            }
        }
        return;
    }

    q0[t] = query[q * D + t];
    __syncthreads();

    if (blockIdx.y == 0) {
        int cg = t & 127, rc = t >> 7;
        const float4* Wv4 = reinterpret_cast<const float4*>(Wv);
        float4 a = make_float4(0.f, 0.f, 0.f, 0.f);
#pragma unroll 8
        for (int i = 0; i < 128; i++) {
            int d = rc * 128 + i;
            float qd = q0[d];
            float4 wv = Wv4[(size_t)d * 128 + cg];
            a.x += qd * wv.x; a.y += qd * wv.y;
            a.z += qd * wv.z; a.w += qd * wv.w;
        }
        part4[rc][cg] = a;
        __syncthreads();
        float tqv = 0.f;
        if (t < 128) {
            float4 r = part4[0][t], p1 = part4[1][t], p2 = part4[2][t], p3 = part4[3][t];
            float4 bv4 = reinterpret_cast<const float4*>(bv)[t];
            r.x += p1.x + p2.x + p3.x + bv4.x;
            r.y += p1.y + p2.y + p3.y + bv4.y;
            r.z += p1.z + p2.z + p3.z + bv4.z;
            r.w += p1.w + p2.w + p3.w + bv4.w;
            reinterpret_cast<float4*>(g_VQ)[q * 128 + t] = r;
            float4 wf = reinterpret_cast<const float4*>(Wf)[t];
            tqv = r.x * wf.x + r.y * wf.y + r.z * wf.z + r.w * wf.w;
        }
#pragma unroll
        for (int o = 16; o; o >>= 1) tqv += __shfl_xor_sync(0xffffffffu, tqv, o);
        if (lane == 0 && w < 4) red[0][w] = tqv;
        __syncthreads();
        if (t == 0) g_tq[q] = red[0][0] + red[0][1] + red[0][2] + red[0][3];
    } else {
        const float4* wr = reinterpret_cast<const float4*>(Wk + (size_t)t * D);
        float a0 = 0.f, a1 = 0.f;
#pragma unroll 8
        for (int i = 0; i < D / 8; i++) {
            float4 w0 = wr[2 * i], w1 = wr[2 * i + 1];
            a0 += w0.x * q0[8*i+0] + w0.y * q0[8*i+1] + w0.z * q0[8*i+2] + w0.w * q0[8*i+3];
            a1 += w1.x * q0[8*i+4] + w1.y * q0[8*i+5] + w1.z * q0[8*i+6] + w1.w * q0[8*i+7];
        }
        float r = a0 + a1;
        g_Ak[q * D + t] = r;
        float r0v = q0[t] * r;
        float r1v = q0[t] * bk[t];
#pragma unroll
        for (int o = 16; o; o >>= 1) {
            r0v += __shfl_xor_sync(0xffffffffu, r0v, o);
            r1v += __shfl_xor_sync(0xffffffffu, r1v, o);
        }
        if (lane == 0) { red[0][w] = r0v; red[1][w] = r1v; }
        __syncthreads();
        if (w == 0) {
            float x0 = (lane < 16) ? red[0][lane] : 0.f;
            float x1 = (lane < 16) ? red[1][lane] : 0.f;
#pragma unroll
            for (int o = 8; o; o >>= 1) {
                x0 += __shfl_xor_sync(0xffffffffu, x0, o);
                x1 += __shfl_xor_sync(0xffffffffu, x1, o);
            }
            if (lane == 0) {
                g_qbk[q] = x1;
                g_sself[q] = (x0 + x1) * SCALE;
            }
        }
    }
}

// ---------------------------------------------------------------------------
// k_sp: scores + pf only (splits moved to k_split). 256 blocks x 512 threads,
// warp = one token row, float4 patch loads + float4 Aks LDS.
// ---------------------------------------------------------------------------
__global__ __launch_bounds__(512) void k_sp(const float* __restrict__ patch) {
    __shared__ __align__(16) float4 Aks4[QN * 128];
    __shared__ __align__(16) float4 us4[128];
    __shared__ float qb[QN];
    __shared__ float cw_s;
    int t = threadIdx.x;
    const float4* g4 = reinterpret_cast<const float4*>(g_Ak);
#pragma unroll
    for (int i = 0; i < 4; i++) Aks4[t + i * 512] = g4[t + i * 512];
    if (t < 128) us4[t] = reinterpret_cast<const float4*>(g_u)[t];
    if (t < QN) qb[t] = g_qbk[t];
    if (t == 0) cw_s = g_cw;
    __syncthreads();

    int w = t >> 5, lane = t & 31;
    int row = blockIdx.x * 16 + w;
    const float4* pr = reinterpret_cast<const float4*>(patch + (size_t)row * D);
    float acc[QN];
    float accu = 0.f;
#pragma unroll
    for (int q = 0; q < QN; q++) acc[q] = 0.f;
#pragma unroll
    for (int c = 0; c < 4; c++) {
        int col = c * 32 + lane;
        float4 pv = pr[col];
        float4 uv = us4[col];
        accu += pv.x * uv.x + pv.y * uv.y + pv.z * uv.z + pv.w * uv.w;
#pragma unroll
        for (int q = 0; q < QN; q++) {
            float4 av = Aks4[q * 128 + col];
            acc[q] += pv.x * av.x + pv.y * av.y + pv.z * av.z + pv.w * av.w;
        }
    }
#pragma unroll
    for (int o = 16; o; o >>= 1) accu += __shfl_xor_sync(0xffffffffu, accu, o);
    if (lane == 0) g_pf[row] = accu + cw_s;
#pragma unroll
    for (int q = 0; q < QN; q++) {
        float v = acc[q];
#pragma unroll
        for (int o = 16; o; o >>= 1) v += __shfl_xor_sync(0xffffffffu, v, o);
        if (lane == 0) g_sp[row * QN + q] = (v + qb[q]) * SCALE;
    }
}

// ---------------------------------------------------------------------------
// k_gemm_mma: Vp = patch @ Wv + bv via mma.sync bf16 (2-term split, 3 products)
// CTA tile 128x64, 256 threads, 2-stage cp.async, 3 CTAs/SM.
// ---------------------------------------------------------------------------
#define OFF_ALO  10240
#define OFF_BHI  20480
#define OFF_BLO  25600
#define STAGE_B  30720
#define SMEM_MMA (2 * STAGE_B)

__global__ __launch_bounds__(256, 3) void k_gemm_mma(const float* __restrict__ bv) {
    extern __shared__ char sm[];
    uint32_t sbase = smem_u32(sm);
    int t = threadIdx.x, wid = t >> 5, lane = t & 31;
    int m0 = blockIdx.y * 128, n0 = blockIdx.x * 64;
    int wm = wid >> 1, wn = wid & 1;

    float acc[2][4][4];
#pragma unroll
    for (int i = 0; i < 2; i++)
#pragma unroll
        for (int j = 0; j < 4; j++)
#pragma unroll
            for (int k = 0; k < 4; k++) acc[i][j][k] = 0.f;

    int rowA[2], segA[2];
#pragma unroll
    for (int h = 0; h < 2; h++) {
        int rem = h * 256 + t;
        rowA[h] = rem >> 2; segA[h] = rem & 3;
    }
    int rowB = t >> 2, segB = t & 3;

    auto load_chunk = [&](int c) {
        int s = c & 1, k0 = c * 32;
        uint32_t base = sbase + s * STAGE_B;
#pragma unroll
        for (int h = 0; h < 2; h++) {
            int r = rowA[h], seg = segA[h];
            size_t go = (size_t)(m0 + r) * D + k0 + seg * 8;
            uint32_t so = (uint32_t)(r * 80 + seg * 16);
            cp16(base + so, g_Ahi + go);
            cp16(base + OFF_ALO + so, g_Alo + go);
        }
        {
            size_t go = (size_t)(n0 + rowB) * D + k0 + segB * 8;
            uint32_t so = (uint32_t)(rowB * 80 + segB * 16);
            cp16(base + OFF_BHI + so, g_Bhi + go);
            cp16(base + OFF_BLO + so, g_Blo + go);
        }
        CP_COMMIT();
    };

    uint32_t aoff = (uint32_t)((wm * 32 + (lane & 15)) * 80 + (lane >> 4) * 16);
    uint32_t boff = (uint32_t)((wn * 32 + (lane & 7) + ((lane >> 4) & 1) * 8) * 80
                               + ((lane >> 3) & 1) * 16);

    load_chunk(0);
    for (int c = 0; c < 16; c++) {
        if (c < 15) { load_chunk(c + 1); CP_WAIT(1); }
        else        { CP_WAIT(0); }
        __syncthreads();
        uint32_t st = sbase + (c & 1) * STAGE_B;
#pragma unroll
        for (int ks = 0; ks < 2; ks++) {
            uint32_t ah[2][4], al[2][4], bh[2][4], bl[2][4];
#pragma unroll
            for (int mt = 0; mt < 2; mt++) {
                ldm_x4(ah[mt], st + aoff + mt * (16 * 80) + ks * 32);
                ldm_x4(al[mt], st + OFF_ALO + aoff + mt * (16 * 80) + ks * 32);
            }
#pragma unroll
            for (int np = 0; np < 2; np++) {
                ldm_x4(bh[np], st + OFF_BHI + boff + np * (16 * 80) + ks * 32);
                ldm_x4(bl[np], st + OFF_BLO + boff + np * (16 * 80) + ks * 32);
            }
#pragma unroll
            for (int mt = 0; mt < 2; mt++)
#pragma unroll
                for (int np = 0; np < 2; np++) {
                    mma16816(acc[mt][2 * np],     ah[mt], &bh[np][0]);
                    mma16816(acc[mt][2 * np + 1], ah[mt], &bh[np][2]);
                    mma16816(acc[mt][2 * np],     ah[mt], &bl[np][0]);
                    mma16816(acc[mt][2 * np + 1], ah[mt], &bl[np][2]);
                    mma16816(acc[mt][2 * np],     al[mt], &bh[np][0]);
                    mma16816(acc[mt][2 * np + 1], al[mt], &bh[np][2]);
                }
        }
        __syncthreads();
    }

    int g = lane >> 2, tig = lane & 3;
#pragma unroll
    for (int mt = 0; mt < 2; mt++) {
        int r = m0 + wm * 32 + mt * 16 + g;
#pragma unroll
        for (int nt = 0; nt < 4; nt++) {
            int col = n0 + wn * 32 + nt * 8 + tig * 2;
            float b0 = __ldg(bv + col), b1 = __ldg(bv + col + 1);
            float2 v0 = make_float2(acc[mt][nt][0] + b0, acc[mt][nt][1] + b1);
            float2 v1 = make_float2(acc[mt][nt][2] + b0, acc[mt][nt][3] + b1);
            *reinterpret_cast<float2*>(&g_Vp[(size_t)r * D + col]) = v0;
            *reinterpret_cast<float2*>(&g_Vp[(size_t)(r + 8) * D + col]) = v1;
        }
    }
}

// ---------------------------------------------------------------------------
// k_weights: one block per group n, 256 threads (8 warps, 2 q each).
// Phases A-D of the collapsed combine -> es[n][64], c0[n][16].
// ---------------------------------------------------------------------------
__global__ __launch_bounds__(256) void k_weights(const int* __restrict__ indices,
                                                 const unsigned* __restrict__ mask,
                                                 const float* __restrict__ bf) {
    __shared__ float S[QN][72];
    __shared__ int sidx[PP];
    __shared__ float pfs[PP];
    __shared__ float tqs[QN];
    __shared__ float invq[QN];
    __shared__ float fq[QN];
    int n = blockIdx.x, t = threadIdx.x;
    int lane = t & 31, w = t >> 5;
    const float NINF = __int_as_float(0xff800000u);

    int myidx = 0;
    if (t < PP) {
        myidx = indices[n * PP + t];
        sidx[t] = myidx;
        g_sidx[n][t] = myidx;
    }
    if (t < QN) tqs[t] = g_tq[t];
    __syncthreads();

    {
        int p = t & 63, qq = t >> 6;
        int idx = sidx[p];
        float4 v;
        if (mask[n * PP + p] != 0u) {
            v = reinterpret_cast<const float4*>(g_sp + (size_t)idx * QN)[qq];
        } else {
            v = make_float4(NINF, NINF, NINF, NINF);
        }
        int q0 = qq * 4;
        S[q0 + 0][p + 1] = v.x; S[q0 + 1][p + 1] = v.y;
        S[q0 + 2][p + 1] = v.z; S[q0 + 3][p + 1] = v.w;
        if (t < PP) pfs[t] = g_pf[myidx];
    }
    if (t < QN) S[t][0] = g_sself[t];
    __syncthreads();

    {
        float bf0 = bf[0];
#pragma unroll
        for (int qi = 0; qi < 2; qi++) {
            int q = w * 2 + qi;
            float v0 = S[q][lane], v1 = S[q][lane + 32];
            float v2 = (lane == 0) ? S[q][64] : NINF;
            float mx = fmaxf(fmaxf(v0, v1), v2);
#pragma unroll
            for (int o = 16; o; o >>= 1) mx = fmaxf(mx, __shfl_xor_sync(0xffffffffu, mx, o));
            float e0 = __expf(v0 - mx), e1 = __expf(v1 - mx);
            float e2 = (lane == 0) ? __expf(v2 - mx) : 0.f;
            float s = e0 + e1 + e2;
#pragma unroll
            for (int o = 16; o; o >>= 1) s += __shfl_xor_sync(0xffffffffu, s, o);
            S[q][lane] = e0; S[q][lane + 32] = e1;
            if (lane == 0) S[q][64] = e2;
            float pr0 = (lane == 0) ? tqs[q] : pfs[lane - 1];
            float fp = e0 * pr0 + e1 * pfs[lane + 31];
            if (lane == 0) fp += e2 * pfs[63];
#pragma unroll
            for (int o = 16; o; o >>= 1) fp += __shfl_xor_sync(0xffffffffu, fp, o);
            if (lane == 0) {
                invq[q] = 1.f / s;
                fq[q] = fp / s + bf0;
            }
        }
    }
    __syncthreads();

    float c[QN];
    {
        float fv[QN], mx = -3.4e38f;
#pragma unroll
        for (int q = 0; q < QN; q++) { fv[q] = fq[q]; mx = fmaxf(mx, fv[q]); }
        float s = 0.f;
#pragma unroll
        for (int q = 0; q < QN; q++) { fv[q] = __expf(fv[q] - mx); s += fv[q]; }
        float inv = 1.f / s;
#pragma unroll
        for (int q = 0; q < QN; q++) c[q] = fv[q] * inv * invq[q];
    }

    if (t < PP) {
        float ep = 0.f;
#pragma unroll
        for (int q = 0; q < QN; q++) ep += c[q] * S[q][t + 1];
        g_es[n][t] = ep;
    }
    if (t < QN) g_c0[n][t] = c[t] * S[t][0];
}

// ---------------------------------------------------------------------------
// k_gather: one block per group n, 256 threads (2 p-halves x 128 cols).
// ---------------------------------------------------------------------------
__global__ __launch_bounds__(256) void k_gather(float* __restrict__ out) {
    __shared__ __align__(16) float4 part[128];
    __shared__ float esb[PP];
    __shared__ float c0b[QN];
    __shared__ int sidx[PP];
    int n = blockIdx.x, t = threadIdx.x;

    if (t < PP) { esb[t] = g_es[n][t]; sidx[t] = g_sidx[n][t]; }
    if (t < QN) c0b[t] = g_c0[n][t];
    __syncthreads();

    int tl = t & 127, half = t >> 7;
    float4 o = make_float4(0.f, 0.f, 0.f, 0.f);
    if (half == 0) {
        const float4* VQ4 = reinterpret_cast<const float4*>(g_VQ);
#pragma unroll
        for (int q = 0; q < QN; q++) {
            float c0 = c0b[q];
            float4 vq = VQ4[q * 128 + tl];
            o.x += c0 * vq.x; o.y += c0 * vq.y;
            o.z += c0 * vq.z; o.w += c0 * vq.w;
        }
    }
    const float4* Vp4 = reinterpret_cast<const float4*>(g_Vp);
#pragma unroll 8
    for (int pi = 0; pi < 32; pi++) {
        int p = half * 32 + pi;
        float4 v = Vp4[(size_t)sidx[p] * 128 + tl];
        float ep = esb[p];
        o.x += ep * v.x; o.y += ep * v.y;
        o.z += ep * v.z; o.w += ep * v.w;
    }
    if (half == 1) part[tl] = o;
    __syncthreads();
    if (half == 0) {
        float4 p1 = part[tl];
        o.x += p1.x; o.y += p1.y; o.z += p1.z; o.w += p1.w;
        reinterpret_cast<float4*>(out)[(size_t)n * 128 + tl] = o;
    }
}

// ---------------------------------------------------------------------------
extern "C" void kernel_launch(void* const* d_in, const int* in_sizes, int n_in,
                              void* d_out, int out_size) {
    (void)in_sizes; (void)n_in; (void)out_size;
    const float* patch   = (const float*)d_in[0];
    const float* query   = (const float*)d_in[1];
    const float* Wk      = (const float*)d_in[2];
    const float* bk      = (const float*)d_in[3];
    const float* Wv      = (const float*)d_in[4];
    const float* bv      = (const float*)d_in[5];
    const float* Wf      = (const float*)d_in[6];
    const float* bf      = (const float*)d_in[7];
    const int* indices   = (const int*)d_in[8];
    const unsigned* mask = (const unsigned*)d_in[9];
    float* out           = (float*)d_out;

    // One-time host-side resources (no device memory involved).
    static cudaStream_t s2 = nullptr;
    static cudaEvent_t evFork = nullptr, evJoin = nullptr;
    if (s2 == nullptr) {
        cudaStreamCreateWithFlags(&s2, cudaStreamNonBlocking);
        cudaEventCreateWithFlags(&evFork, cudaEventDisableTiming);
        cudaEventCreateWithFlags(&evJoin, cudaEventDisableTiming);
        cudaFuncSetAttribute(k_gemm_mma, cudaFuncAttributeMaxDynamicSharedMemorySize, SMEM_MMA);
    }

    // Fork immediately: side stream runs splits -> GEMM (depends only on
    // inputs); main stream runs pre -> sp -> weights. Join before gather.
    cudaEventRecord(evFork, 0);
    cudaStreamWaitEvent(s2, evFork, 0);

    k_split<<<2048 + 64, 256, 0, s2>>>(patch, Wv);
    k_gemm_mma<<<dim3(8, 32), 256, SMEM_MMA, s2>>>(bv);
    cudaEventRecord(evJoin, s2);

    k_pre<<<dim3(QN, 3), D>>>(query, Wk, Wv, bv, bk, Wf);
    k_sp<<<NT / 16, 512>>>(patch);
    k_weights<<<NG, 256>>>(indices, mask, bf);

    cudaStreamWaitEvent(0, evJoin, 0);
    k_gather<<<NG, 256>>>(out);
}

// round 17
// speedup vs baseline: 1.3928x; 1.0321x over previous
#include <cuda_runtime.h>
#include <cuda_bf16.h>
#include <math.h>
#include <stdint.h>

// Problem constants
#define D   512
#define QN  16
#define NT  4096   // B*L tokens
#define NG  512    // N gathered groups
#define PP  64     // group size P

#define SCALE 0.04419417382415922f  // 1/sqrt(512)

// Scratch (allocation-free: __device__ globals)
__device__ float g_Vp[NT * D];            // patch @ Wv + bv      [4096,512]
__device__ __nv_bfloat16 g_Ahi[NT * D];   // bf16 hi split of patch
__device__ __nv_bfloat16 g_Alo[NT * D];   // bf16 lo split of patch
__device__ __nv_bfloat16 g_Bhi[D * D];    // bf16 hi split of Wv^T ([n][k])
__device__ __nv_bfloat16 g_Blo[D * D];    // bf16 lo split of Wv^T
__device__ float g_sp[NT * QN];           // scaled patch scores  [4096,16]
__device__ float g_VQ[QN * D];            // Q0 @ Wv + bv         [16,512]
__device__ float g_Ak[QN * D];            // (Wk @ Q0^T)^T        [16,512]
__device__ float g_pf[NT];                // pf[t] = patch[t].u + cw (== Vp.Wf)
__device__ float g_u[D];                  // Wv @ Wf              [512]
__device__ float g_cw;                    // bv . Wf
__device__ float g_tq[QN];                // VQ @ Wf              [16]
__device__ float g_sself[QN];             // self-token scores    [16]
__device__ float g_qbk[QN];               // Q0[q] . bk           [16]
__device__ float g_es[NG][PP];            // effective gather weights
__device__ float g_c0[NG][QN];            // VQ-term coefficients
__device__ int   g_sidx[NG][PP];          // cached indices

// ---- PTX helpers (all sm_80-level, valid for compute_103 target) -----------
__device__ __forceinline__ uint32_t smem_u32(const void* p) {
    uint32_t a;
    asm("{ .reg .u64 tmp; cvta.to.shared.u64 tmp, %1; cvt.u32.u64 %0, tmp; }"
        : "=r"(a) : "l"(p));
    return a;
}
__device__ __forceinline__ void cp16(uint32_t sdst, const void* gsrc) {
    asm volatile("cp.async.cg.shared.global [%0], [%1], 16;"
                 :: "r"(sdst), "l"(gsrc) : "memory");
}
#define CP_COMMIT() asm volatile("cp.async.commit_group;" ::: "memory")
#define CP_WAIT(n)  asm volatile("cp.async.wait_group %0;" :: "n"(n) : "memory")

__device__ __forceinline__ void ldm_x4(uint32_t* r, uint32_t addr) {
    asm volatile("ldmatrix.sync.aligned.m8n8.x4.shared.b16 {%0,%1,%2,%3}, [%4];"
                 : "=r"(r[0]), "=r"(r[1]), "=r"(r[2]), "=r"(r[3]) : "r"(addr));
}
__device__ __forceinline__ void mma16816(float* c, const uint32_t* a, const uint32_t* b) {
    asm volatile("mma.sync.aligned.m16n8k16.row.col.f32.bf16.bf16.f32 "
                 "{%0,%1,%2,%3}, {%4,%5,%6,%7}, {%8,%9}, {%0,%1,%2,%3};"
                 : "+f"(c[0]), "+f"(c[1]), "+f"(c[2]), "+f"(c[3])
                 : "r"(a[0]), "r"(a[1]), "r"(a[2]), "r"(a[3]), "r"(b[0]), "r"(b[1]));
}

// ---------------------------------------------------------------------------
// k_split (side stream): blocks 0..2047: bf16 hi/lo split of patch.
// Blocks 2048..2111: Wv transpose + bf16 hi/lo splits.
// ---------------------------------------------------------------------------
__global__ __launch_bounds__(256) void k_split(const float* __restrict__ patch,
                                               const float* __restrict__ Wv) {
    if (blockIdx.x < 2048) {
        int i = blockIdx.x * 256 + threadIdx.x;
        float4 v = reinterpret_cast<const float4*>(patch)[i];
        __nv_bfloat162 h0, h1, l0, l1;
        h0.x = __float2bfloat16_rn(v.x); l0.x = __float2bfloat16_rn(v.x - __bfloat162float(h0.x));
        h0.y = __float2bfloat16_rn(v.y); l0.y = __float2bfloat16_rn(v.y - __bfloat162float(h0.y));
        h1.x = __float2bfloat16_rn(v.z); l1.x = __float2bfloat16_rn(v.z - __bfloat162float(h1.x));
        h1.y = __float2bfloat16_rn(v.w); l1.y = __float2bfloat16_rn(v.w - __bfloat162float(h1.y));
        reinterpret_cast<__nv_bfloat162*>(g_Ahi)[2 * i]     = h0;
        reinterpret_cast<__nv_bfloat162*>(g_Ahi)[2 * i + 1] = h1;
        reinterpret_cast<__nv_bfloat162*>(g_Alo)[2 * i]     = l0;
        reinterpret_cast<__nv_bfloat162*>(g_Alo)[2 * i + 1] = l1;
    } else {
        __shared__ float tile[64][65];
        int b = blockIdx.x - 2048;
        int c0 = (b & 7) * 64, r0 = (b >> 3) * 64;
        int j = threadIdx.x & 63, i0 = threadIdx.x >> 6;
#pragma unroll
        for (int k = 0; k < 16; k++) {
            int i = i0 + k * 4;
            tile[i][j] = Wv[(size_t)(r0 + i) * D + c0 + j];
        }
        __syncthreads();
#pragma unroll
        for (int k = 0; k < 16; k++) {
            int i = i0 + k * 4;
            float v = tile[j][i];
            size_t o = (size_t)(c0 + i) * D + r0 + j;
            __nv_bfloat16 h = __float2bfloat16_rn(v);
            g_Bhi[o] = h;
            g_Blo[o] = __float2bfloat16_rn(v - __bfloat162float(h));
        }
    }
}

// ---------------------------------------------------------------------------
// k_pre: grid (16, 3), block 512.
//  y==0: VQ[q] + tq[q];  y==1: Ak[q] + qbk/sself;  y==2: u = Wv@Wf, cw = bv.Wf
// ---------------------------------------------------------------------------
__global__ void k_pre(const float* __restrict__ query, const float* __restrict__ Wk,
                      const float* __restrict__ Wv, const float* __restrict__ bv,
                      const float* __restrict__ bk, const float* __restrict__ Wf) {
    __shared__ float q0[D];
    __shared__ float red[2][16];
    __shared__ __align__(16) float4 part4[4][128];
    int q = blockIdx.x, t = threadIdx.x;
    int w = t >> 5, lane = t & 31;

    if (blockIdx.y == 2) {
        q0[t] = Wf[t];
        __syncthreads();
#pragma unroll
        for (int hh = 0; hh < 2; hh++) {
            int r = blockIdx.x * 32 + hh * 16 + w;
            const float* row = Wv + (size_t)r * D;
            float s = 0.f;
#pragma unroll
            for (int i = 0; i < D / 32; i++) s += row[lane + i * 32] * q0[lane + i * 32];
#pragma unroll
            for (int o = 16; o; o >>= 1) s += __shfl_xor_sync(0xffffffffu, s, o);
            if (lane == 0) g_u[r] = s;
        }
        if (blockIdx.x == 0) {
            float r1 = bv[t] * q0[t];
#pragma unroll
            for (int o = 16; o; o >>= 1) r1 += __shfl_xor_sync(0xffffffffu, r1, o);
            if (lane == 0) red[0][w] = r1;
            __syncthreads();
            if (t == 0) {
                float s = 0.f;
#pragma unroll
                for (int i = 0; i < 16; i++) s += red[0][i];
                g_cw = s;
            }
        }
        return;
    }

    q0[t] = query[q * D + t];
    __syncthreads();

    if (blockIdx.y == 0) {
        int cg = t & 127, rc = t >> 7;
        const float4* Wv4 = reinterpret_cast<const float4*>(Wv);
        float4 a = make_float4(0.f, 0.f, 0.f, 0.f);
#pragma unroll 8
        for (int i = 0; i < 128; i++) {
            int d = rc * 128 + i;
            float qd = q0[d];
            float4 wv = Wv4[(size_t)d * 128 + cg];
            a.x += qd * wv.x; a.y += qd * wv.y;
            a.z += qd * wv.z; a.w += qd * wv.w;
        }
        part4[rc][cg] = a;
        __syncthreads();
        float tqv = 0.f;
        if (t < 128) {
            float4 r = part4[0][t], p1 = part4[1][t], p2 = part4[2][t], p3 = part4[3][t];
            float4 bv4 = reinterpret_cast<const float4*>(bv)[t];
            r.x += p1.x + p2.x + p3.x + bv4.x;
            r.y += p1.y + p2.y + p3.y + bv4.y;
            r.z += p1.z + p2.z + p3.z + bv4.z;
            r.w += p1.w + p2.w + p3.w + bv4.w;
            reinterpret_cast<float4*>(g_VQ)[q * 128 + t] = r;
            float4 wf = reinterpret_cast<const float4*>(Wf)[t];
            tqv = r.x * wf.x + r.y * wf.y + r.z * wf.z + r.w * wf.w;
        }
#pragma unroll
        for (int o = 16; o; o >>= 1) tqv += __shfl_xor_sync(0xffffffffu, tqv, o);
        if (lane == 0 && w < 4) red[0][w] = tqv;
        __syncthreads();
        if (t == 0) g_tq[q] = red[0][0] + red[0][1] + red[0][2] + red[0][3];
    } else {
        const float4* wr = reinterpret_cast<const float4*>(Wk + (size_t)t * D);
        float a0 = 0.f, a1 = 0.f;
#pragma unroll 8
        for (int i = 0; i < D / 8; i++) {
            float4 w0 = wr[2 * i], w1 = wr[2 * i + 1];
            a0 += w0.x * q0[8*i+0] + w0.y * q0[8*i+1] + w0.z * q0[8*i+2] + w0.w * q0[8*i+3];
            a1 += w1.x * q0[8*i+4] + w1.y * q0[8*i+5] + w1.z * q0[8*i+6] + w1.w * q0[8*i+7];
        }
        float r = a0 + a1;
        g_Ak[q * D + t] = r;
        float r0v = q0[t] * r;
        float r1v = q0[t] * bk[t];
#pragma unroll
        for (int o = 16; o; o >>= 1) {
            r0v += __shfl_xor_sync(0xffffffffu, r0v, o);
            r1v += __shfl_xor_sync(0xffffffffu, r1v, o);
        }
        if (lane == 0) { red[0][w] = r0v; red[1][w] = r1v; }
        __syncthreads();
        if (w == 0) {
            float x0 = (lane < 16) ? red[0][lane] : 0.f;
            float x1 = (lane < 16) ? red[1][lane] : 0.f;
#pragma unroll
            for (int o = 8; o; o >>= 1) {
                x0 += __shfl_xor_sync(0xffffffffu, x0, o);
                x1 += __shfl_xor_sync(0xffffffffu, x1, o);
            }
            if (lane == 0) {
                g_qbk[q] = x1;
                g_sself[q] = (x0 + x1) * SCALE;
            }
        }
    }
}

// ---------------------------------------------------------------------------
// k_sp: scores + pf. grid 256 x 256 threads. Each warp processes TWO token
// rows so every Aks smem read feeds two FMA chains (halves LDS traffic).
// ---------------------------------------------------------------------------
__global__ __launch_bounds__(256) void k_sp(const float* __restrict__ patch) {
    __shared__ __align__(16) float4 Aks4[QN * 128];
    __shared__ __align__(16) float4 us4[128];
    __shared__ float qb[QN];
    __shared__ float cw_s;
    int t = threadIdx.x;
    const float4* g4 = reinterpret_cast<const float4*>(g_Ak);
#pragma unroll
    for (int i = 0; i < 8; i++) Aks4[t + i * 256] = g4[t + i * 256];
    if (t < 128) us4[t] = reinterpret_cast<const float4*>(g_u)[t];
    if (t < QN) qb[t] = g_qbk[t];
    if (t == 0) cw_s = g_cw;
    __syncthreads();

    int w = t >> 5, lane = t & 31;
    int row0 = blockIdx.x * 16 + w * 2;
    const float4* pr0 = reinterpret_cast<const float4*>(patch + (size_t)row0 * D);
    const float4* pr1 = reinterpret_cast<const float4*>(patch + (size_t)(row0 + 1) * D);
    float acc0[QN], acc1[QN];
    float au0 = 0.f, au1 = 0.f;
#pragma unroll
    for (int q = 0; q < QN; q++) { acc0[q] = 0.f; acc1[q] = 0.f; }
#pragma unroll
    for (int c = 0; c < 4; c++) {
        int col = c * 32 + lane;
        float4 p0 = pr0[col];
        float4 p1 = pr1[col];
        float4 uv = us4[col];
        au0 += p0.x * uv.x + p0.y * uv.y + p0.z * uv.z + p0.w * uv.w;
        au1 += p1.x * uv.x + p1.y * uv.y + p1.z * uv.z + p1.w * uv.w;
#pragma unroll
        for (int q = 0; q < QN; q++) {
            float4 av = Aks4[q * 128 + col];
            acc0[q] += p0.x * av.x + p0.y * av.y + p0.z * av.z + p0.w * av.w;
            acc1[q] += p1.x * av.x + p1.y * av.y + p1.z * av.z + p1.w * av.w;
        }
    }
#pragma unroll
    for (int o = 16; o; o >>= 1) {
        au0 += __shfl_xor_sync(0xffffffffu, au0, o);
        au1 += __shfl_xor_sync(0xffffffffu, au1, o);
    }
    if (lane == 0) { g_pf[row0] = au0 + cw_s; g_pf[row0 + 1] = au1 + cw_s; }
#pragma unroll
    for (int q = 0; q < QN; q++) {
        float v0 = acc0[q], v1 = acc1[q];
#pragma unroll
        for (int o = 16; o; o >>= 1) {
            v0 += __shfl_xor_sync(0xffffffffu, v0, o);
            v1 += __shfl_xor_sync(0xffffffffu, v1, o);
        }
        if (lane == 0) {
            g_sp[row0 * QN + q] = (v0 + qb[q]) * SCALE;
            g_sp[(row0 + 1) * QN + q] = (v1 + qb[q]) * SCALE;
        }
    }
}

// ---------------------------------------------------------------------------
// k_gemm_mma: Vp = patch @ Wv + bv via mma.sync bf16 (2-term split, 3 products)
// CTA tile 128x64, 256 threads, 2-stage cp.async, 3 CTAs/SM.
// ---------------------------------------------------------------------------
#define OFF_ALO  10240
#define OFF_BHI  20480
#define OFF_BLO  25600
#define STAGE_B  30720
#define SMEM_MMA (2 * STAGE_B)

__global__ __launch_bounds__(256, 3) void k_gemm_mma(const float* __restrict__ bv) {
    extern __shared__ char sm[];
    uint32_t sbase = smem_u32(sm);
    int t = threadIdx.x, wid = t >> 5, lane = t & 31;
    int m0 = blockIdx.y * 128, n0 = blockIdx.x * 64;
    int wm = wid >> 1, wn = wid & 1;

    float acc[2][4][4];
#pragma unroll
    for (int i = 0; i < 2; i++)
#pragma unroll
        for (int j = 0; j < 4; j++)
#pragma unroll
            for (int k = 0; k < 4; k++) acc[i][j][k] = 0.f;

    int rowA[2], segA[2];
#pragma unroll
    for (int h = 0; h < 2; h++) {
        int rem = h * 256 + t;
        rowA[h] = rem >> 2; segA[h] = rem & 3;
    }
    int rowB = t >> 2, segB = t & 3;

    auto load_chunk = [&](int c) {
        int s = c & 1, k0 = c * 32;
        uint32_t base = sbase + s * STAGE_B;
#pragma unroll
        for (int h = 0; h < 2; h++) {
            int r = rowA[h], seg = segA[h];
            size_t go = (size_t)(m0 + r) * D + k0 + seg * 8;
            uint32_t so = (uint32_t)(r * 80 + seg * 16);
            cp16(base + so, g_Ahi + go);
            cp16(base + OFF_ALO + so, g_Alo + go);
        }
        {
            size_t go = (size_t)(n0 + rowB) * D + k0 + segB * 8;
            uint32_t so = (uint32_t)(rowB * 80 + segB * 16);
            cp16(base + OFF_BHI + so, g_Bhi + go);
            cp16(base + OFF_BLO + so, g_Blo + go);
        }
        CP_COMMIT();
    };

    uint32_t aoff = (uint32_t)((wm * 32 + (lane & 15)) * 80 + (lane >> 4) * 16);
    uint32_t boff = (uint32_t)((wn * 32 + (lane & 7) + ((lane >> 4) & 1) * 8) * 80
                               + ((lane >> 3) & 1) * 16);

    load_chunk(0);
    for (int c = 0; c < 16; c++) {
        if (c < 15) { load_chunk(c + 1); CP_WAIT(1); }
        else        { CP_WAIT(0); }
        __syncthreads();
        uint32_t st = sbase + (c & 1) * STAGE_B;
#pragma unroll
        for (int ks = 0; ks < 2; ks++) {
            uint32_t ah[2][4], al[2][4], bh[2][4], bl[2][4];
#pragma unroll
            for (int mt = 0; mt < 2; mt++) {
                ldm_x4(ah[mt], st + aoff + mt * (16 * 80) + ks * 32);
                ldm_x4(al[mt], st + OFF_ALO + aoff + mt * (16 * 80) + ks * 32);
            }
#pragma unroll
            for (int np = 0; np < 2; np++) {
                ldm_x4(bh[np], st + OFF_BHI + boff + np * (16 * 80) + ks * 32);
                ldm_x4(bl[np], st + OFF_BLO + boff + np * (16 * 80) + ks * 32);
            }
#pragma unroll
            for (int mt = 0; mt < 2; mt++)
#pragma unroll
                for (int np = 0; np < 2; np++) {
                    mma16816(acc[mt][2 * np],     ah[mt], &bh[np][0]);
                    mma16816(acc[mt][2 * np + 1], ah[mt], &bh[np][2]);
                    mma16816(acc[mt][2 * np],     ah[mt], &bl[np][0]);
                    mma16816(acc[mt][2 * np + 1], ah[mt], &bl[np][2]);
                    mma16816(acc[mt][2 * np],     al[mt], &bh[np][0]);
                    mma16816(acc[mt][2 * np + 1], al[mt], &bh[np][2]);
                }
        }
        __syncthreads();
    }

    int g = lane >> 2, tig = lane & 3;
#pragma unroll
    for (int mt = 0; mt < 2; mt++) {
        int r = m0 + wm * 32 + mt * 16 + g;
#pragma unroll
        for (int nt = 0; nt < 4; nt++) {
            int col = n0 + wn * 32 + nt * 8 + tig * 2;
            float b0 = __ldg(bv + col), b1 = __ldg(bv + col + 1);
            float2 v0 = make_float2(acc[mt][nt][0] + b0, acc[mt][nt][1] + b1);
            float2 v1 = make_float2(acc[mt][nt][2] + b0, acc[mt][nt][3] + b1);
            *reinterpret_cast<float2*>(&g_Vp[(size_t)r * D + col]) = v0;
            *reinterpret_cast<float2*>(&g_Vp[(size_t)(r + 8) * D + col]) = v1;
        }
    }
}

// ---------------------------------------------------------------------------
// k_weights: one block per group n, 256 threads (8 warps, 2 q each).
// Phases A-D of the collapsed combine -> es[n][64], c0[n][16].
// ---------------------------------------------------------------------------
__global__ __launch_bounds__(256) void k_weights(const int* __restrict__ indices,
                                                 const unsigned* __restrict__ mask,
                                                 const float* __restrict__ bf) {
    __shared__ float S[QN][72];
    __shared__ int sidx[PP];
    __shared__ float pfs[PP];
    __shared__ float tqs[QN];
    __shared__ float invq[QN];
    __shared__ float fq[QN];
    int n = blockIdx.x, t = threadIdx.x;
    int lane = t & 31, w = t >> 5;
    const float NINF = __int_as_float(0xff800000u);

    int myidx = 0;
    if (t < PP) {
        myidx = indices[n * PP + t];
        sidx[t] = myidx;
        g_sidx[n][t] = myidx;
    }
    if (t < QN) tqs[t] = g_tq[t];
    __syncthreads();

    {
        int p = t & 63, qq = t >> 6;
        int idx = sidx[p];
        float4 v;
        if (mask[n * PP + p] != 0u) {
            v = reinterpret_cast<const float4*>(g_sp + (size_t)idx * QN)[qq];
        } else {
            v = make_float4(NINF, NINF, NINF, NINF);
        }
        int q0 = qq * 4;
        S[q0 + 0][p + 1] = v.x; S[q0 + 1][p + 1] = v.y;
        S[q0 + 2][p + 1] = v.z; S[q0 + 3][p + 1] = v.w;
        if (t < PP) pfs[t] = g_pf[myidx];
    }
    if (t < QN) S[t][0] = g_sself[t];
    __syncthreads();

    {
        float bf0 = bf[0];
#pragma unroll
        for (int qi = 0; qi < 2; qi++) {
            int q = w * 2 + qi;
            float v0 = S[q][lane], v1 = S[q][lane + 32];
            float v2 = (lane == 0) ? S[q][64] : NINF;
            float mx = fmaxf(fmaxf(v0, v1), v2);
#pragma unroll
            for (int o = 16; o; o >>= 1) mx = fmaxf(mx, __shfl_xor_sync(0xffffffffu, mx, o));
            float e0 = __expf(v0 - mx), e1 = __expf(v1 - mx);
            float e2 = (lane == 0) ? __expf(v2 - mx) : 0.f;
            float s = e0 + e1 + e2;
#pragma unroll
            for (int o = 16; o; o >>= 1) s += __shfl_xor_sync(0xffffffffu, s, o);
            S[q][lane] = e0; S[q][lane + 32] = e1;
            if (lane == 0) S[q][64] = e2;
            float pr0 = (lane == 0) ? tqs[q] : pfs[lane - 1];
            float fp = e0 * pr0 + e1 * pfs[lane + 31];
            if (lane == 0) fp += e2 * pfs[63];
#pragma unroll
            for (int o = 16; o; o >>= 1) fp += __shfl_xor_sync(0xffffffffu, fp, o);
            if (lane == 0) {
                invq[q] = 1.f / s;
                fq[q] = fp / s + bf0;
            }
        }
    }
    __syncthreads();

    float c[QN];
    {
        float fv[QN], mx = -3.4e38f;
#pragma unroll
        for (int q = 0; q < QN; q++) { fv[q] = fq[q]; mx = fmaxf(mx, fv[q]); }
        float s = 0.f;
#pragma unroll
        for (int q = 0; q < QN; q++) { fv[q] = __expf(fv[q] - mx); s += fv[q]; }
        float inv = 1.f / s;
#pragma unroll
        for (int q = 0; q < QN; q++) c[q] = fv[q] * inv * invq[q];
    }

    if (t < PP) {
        float ep = 0.f;
#pragma unroll
        for (int q = 0; q < QN; q++) ep += c[q] * S[q][t + 1];
        g_es[n][t] = ep;
    }
    if (t < QN) g_c0[n][t] = c[t] * S[t][0];
}

// ---------------------------------------------------------------------------
// k_gather: one block per group n, 256 threads (2 p-halves x 128 cols).
// ---------------------------------------------------------------------------
__global__ __launch_bounds__(256) void k_gather(float* __restrict__ out) {
    __shared__ __align__(16) float4 part[128];
    __shared__ float esb[PP];
    __shared__ float c0b[QN];
    __shared__ int sidx[PP];
    int n = blockIdx.x, t = threadIdx.x;

    if (t < PP) { esb[t] = g_es[n][t]; sidx[t] = g_sidx[n][t]; }
    if (t < QN) c0b[t] = g_c0[n][t];
    __syncthreads();

    int tl = t & 127, half = t >> 7;
    float4 o = make_float4(0.f, 0.f, 0.f, 0.f);
    if (half == 0) {
        const float4* VQ4 = reinterpret_cast<const float4*>(g_VQ);
#pragma unroll
        for (int q = 0; q < QN; q++) {
            float c0 = c0b[q];
            float4 vq = VQ4[q * 128 + tl];
            o.x += c0 * vq.x; o.y += c0 * vq.y;
            o.z += c0 * vq.z; o.w += c0 * vq.w;
        }
    }
    const float4* Vp4 = reinterpret_cast<const float4*>(g_Vp);
#pragma unroll 8
    for (int pi = 0; pi < 32; pi++) {
        int p = half * 32 + pi;
        float4 v = Vp4[(size_t)sidx[p] * 128 + tl];
        float ep = esb[p];
        o.x += ep * v.x; o.y += ep * v.y;
        o.z += ep * v.z; o.w += ep * v.w;
    }
    if (half == 1) part[tl] = o;
    __syncthreads();
    if (half == 0) {
        float4 p1 = part[tl];
        o.x += p1.x; o.y += p1.y; o.z += p1.z; o.w += p1.w;
        reinterpret_cast<float4*>(out)[(size_t)n * 128 + tl] = o;
    }
}

// ---------------------------------------------------------------------------
extern "C" void kernel_launch(void* const* d_in, const int* in_sizes, int n_in,
                              void* d_out, int out_size) {
    (void)in_sizes; (void)n_in; (void)out_size;
    const float* patch   = (const float*)d_in[0];
    const float* query   = (const float*)d_in[1];
    const float* Wk      = (const float*)d_in[2];
    const float* bk      = (const float*)d_in[3];
    const float* Wv      = (const float*)d_in[4];
    const float* bv      = (const float*)d_in[5];
    const float* Wf      = (const float*)d_in[6];
    const float* bf      = (const float*)d_in[7];
    const int* indices   = (const int*)d_in[8];
    const unsigned* mask = (const unsigned*)d_in[9];
    float* out           = (float*)d_out;

    // One-time host-side resources (no device memory involved).
    static cudaStream_t s2 = nullptr;
    static cudaEvent_t evFork = nullptr, evJoin = nullptr;
    if (s2 == nullptr) {
        cudaStreamCreateWithFlags(&s2, cudaStreamNonBlocking);
        cudaEventCreateWithFlags(&evFork, cudaEventDisableTiming);
        cudaEventCreateWithFlags(&evJoin, cudaEventDisableTiming);
        cudaFuncSetAttribute(k_gemm_mma, cudaFuncAttributeMaxDynamicSharedMemorySize, SMEM_MMA);
    }

    // Fork: side stream runs splits -> GEMM (input-only deps);
    // main stream runs pre -> sp -> weights. Join before gather.
    cudaEventRecord(evFork, 0);
    cudaStreamWaitEvent(s2, evFork, 0);

    k_split<<<2048 + 64, 256, 0, s2>>>(patch, Wv);
    k_gemm_mma<<<dim3(8, 32), 256, SMEM_MMA, s2>>>(bv);
    cudaEventRecord(evJoin, s2);

    k_pre<<<dim3(QN, 3), D>>>(query, Wk, Wv, bv, bk, Wf);
    k_sp<<<NT / 16, 256>>>(patch);
    k_weights<<<NG, 256>>>(indices, mask, bf);

    cudaStreamWaitEvent(0, evJoin, 0);
    k_gather<<<NG, 256>>>(out);
}